// round 9
// baseline (speedup 1.0000x reference)
#include <cuda_runtime.h>
#include <cuda_fp16.h>

#define NN 100000
#define NE 1600000
#define IN_CH 128
#define HID 64
#define LAT 32

#define SCAN_BLK 512
#define SCAN_NB ((NN + SCAN_BLK - 1) / SCAN_BLK)   // 196
#define NEP (NE + 8 * NN)                          // padded edge capacity

// Scratch (static __device__ — no allocations allowed)
__device__ int     g_stride;            // 1 = edge_index is int32, 2 = int64
__device__ int     g_deg[NN];
__device__ int     g_rowptr[NN + 1];    // padded CSR offsets (multiples of 8)
__device__ int     g_cursor[NN];
__device__ int     g_blocksums[SCAN_NB];
__device__ float4  g_edgebuf[NEP / 2];  // paired records {s0,n0,s1,n1}
__device__ float   g_dis[NN];
__device__ __half2 g_ha[NN * 32];       // h1 = x@W1 fp16 (agg1 gather input)
__device__ __half2 g_hb[NN * 32];       // relu(agg1+b1) fp16 (agg2 gather input)
__device__ float   g_f[NN * HID];       // agg2 output fp32 (gemm2 input)

struct alignas(16) H8 { __half2 h[4]; };

// ---------------------------------------------------------------------------
__device__ __forceinline__ void ffma2(unsigned long long& acc,
                                      unsigned long long a,
                                      unsigned long long b) {
    asm("fma.rn.f32x2 %0, %1, %2, %0;" : "+l"(acc) : "l"(a), "l"(b));
}
__device__ __forceinline__ unsigned long long pack2(float v) {
    unsigned long long r;
    asm("mov.b64 %0, {%1, %1};" : "=l"(r) : "f"(v));
    return r;
}
__device__ __forceinline__ void unpack2(unsigned long long p, float& lo, float& hi) {
    asm("mov.b64 {%0, %1}, %2;" : "=f"(lo), "=f"(hi) : "l"(p));
}

// ---------------------------------------------------------------------------
// Zero degrees; block 0 warp 0 detects edge_index dtype (int64 → odd words 0).
__global__ void k_zero_detect(const int* __restrict__ ei) {
    int i = blockIdx.x * blockDim.x + threadIdx.x;
    if (i < NN) g_deg[i] = 0;
    if (blockIdx.x == 0 && threadIdx.x < 32) {
        int lane = threadIdx.x;
        int v = ei[2 * lane + 1];
        unsigned m = __ballot_sync(0xffffffffu, v != 0);
        if (lane == 0) g_stride = (m == 0u) ? 2 : 1;
    }
}

__global__ void k_count_deg(const int* __restrict__ ei) {
    int e = blockIdx.x * blockDim.x + threadIdx.x;
    if (e >= NE) return;
    int st = g_stride;
    int c = ei[(size_t)st * NE + (size_t)e * st];   // target node
    atomicAdd(&g_deg[c], 1);
}

// Per-block exclusive scan of PADDED degrees -> g_rowptr (local part).
__global__ void k_scan_local() {
    __shared__ int s[SCAN_BLK];
    int t = threadIdx.x;
    int i = blockIdx.x * SCAN_BLK + t;
    int v = (i < NN) ? ((g_deg[i] + 7) & ~7) : 0;   // pad to multiple of 8
    s[t] = v;
    __syncthreads();
#pragma unroll
    for (int off = 1; off < SCAN_BLK; off <<= 1) {
        int add = (t >= off) ? s[t - off] : 0;
        __syncthreads();
        s[t] += add;
        __syncthreads();
    }
    if (i < NN) g_rowptr[i] = s[t] - v;   // exclusive (local)
    if (t == SCAN_BLK - 1) g_blocksums[blockIdx.x] = s[t];
}

// Finalize: every block redundantly scans the 196 block sums in smem, then
// rowptr += prefix; cursor = rowptr; dis = rsqrt(deg+1); zero pad records.
__global__ void k_finalize_csr() {
    __shared__ int s[256];
    int t = threadIdx.x;
    int bv = (t < SCAN_NB) ? g_blocksums[t] : 0;
    s[t] = bv;
    __syncthreads();
#pragma unroll
    for (int off = 1; off < 256; off <<= 1) {
        int add = (t >= off) ? s[t - off] : 0;
        __syncthreads();
        s[t] += add;
        __syncthreads();
    }
    // s[k] is now the INCLUSIVE prefix of blocksums.
    int i = blockIdx.x * blockDim.x + t;
    if (i < NN) {
        int sb = i >> 9;                         // which scan block
        int prefix = (sb > 0) ? s[sb - 1] : 0;   // exclusive prefix
        int rp = g_rowptr[i] + prefix;
        g_rowptr[i] = rp;
        g_cursor[i] = rp;
        int deg = g_deg[i];
        g_dis[i] = rsqrtf((float)deg + 1.0f);
        int pdeg = (deg + 7) & ~7;
        float2* ed = (float2*)g_edgebuf;
        for (int j = rp + deg; j < rp + pdeg; j++)
            ed[j] = make_float2(0.0f, 0.0f);     // src=0 (bits), norm=0
    }
    if (i == 0) g_rowptr[NN] = s[SCAN_NB - 1];   // total padded edges
}

// Scatter edges into destination-sorted padded order as fused 8B records.
__global__ void k_scatter(const int* __restrict__ ei) {
    int e = blockIdx.x * blockDim.x + threadIdx.x;
    if (e >= NE) return;
    int st = g_stride;
    int r = ei[(size_t)e * st];                     // source
    int c = ei[(size_t)st * NE + (size_t)e * st];   // target
    int pos = atomicAdd(&g_cursor[c], 1);
    ((float2*)g_edgebuf)[pos] = make_float2(__int_as_float(r), g_dis[r] * g_dis[c]);
}

// ---------------------------------------------------------------------------
// h1 = x @ W1  (100000x128 @ 128x64), output fp16 to g_ha.
// 256 threads; each block does 64 rows in TWO 32-row phases sharing one W load.
__global__ void k_gemm1(const float* __restrict__ x, const float* __restrict__ W) {
    __shared__ alignas(16) float sW[IN_CH * HID];   // 32 KB, [k][c]
    __shared__ alignas(16) float sX[32 * IN_CH];    // 16 KB, swizzled [r][k^r]
    int tid = threadIdx.x;
    int base0 = blockIdx.x * 64;

    for (int i = tid; i < IN_CH * HID; i += 256) sW[i] = W[i];

    int r = tid & 31;
    int c0 = (tid >> 5) * 8;

#pragma unroll
    for (int phase = 0; phase < 2; phase++) {
        int node0 = base0 + phase * 32;
        __syncthreads();   // sW ready (phase 0) / previous compute done (phase 1)
        for (int i = tid; i < 32 * IN_CH; i += 256) {
            int rr = i >> 7, k = i & 127;
            int row = node0 + rr;
            if (row >= NN) row = NN - 1;            // safe pad (store guarded)
            sX[rr * IN_CH + (k ^ rr)] = x[(size_t)row * IN_CH + k];
        }
        __syncthreads();

        unsigned long long acc[4] = {0ull, 0ull, 0ull, 0ull};
#pragma unroll 4
        for (int k = 0; k < IN_CH; k++) {
            unsigned long long xp = pack2(sX[r * IN_CH + (k ^ r)]);
            ulonglong2 w0 = *reinterpret_cast<const ulonglong2*>(&sW[k * HID + c0]);
            ulonglong2 w1 = *reinterpret_cast<const ulonglong2*>(&sW[k * HID + c0 + 4]);
            ffma2(acc[0], xp, w0.x);
            ffma2(acc[1], xp, w0.y);
            ffma2(acc[2], xp, w1.x);
            ffma2(acc[3], xp, w1.y);
        }

        int node = node0 + r;
        if (node < NN) {
            float o[8];
#pragma unroll
            for (int j = 0; j < 4; j++) unpack2(acc[j], o[2 * j], o[2 * j + 1]);
            H8 v;
#pragma unroll
            for (int j = 0; j < 4; j++)
                v.h[j] = __floats2half2_rn(o[2 * j], o[2 * j + 1]);
            *reinterpret_cast<H8*>(&g_ha[(size_t)node * 32 + (c0 >> 1)]) = v;
        }
    }
}

// ---------------------------------------------------------------------------
// CSR aggregation over PADDED segments (exact multiples of 8 edges).
// WARP per node: 32 lanes × half2 = 64 channels; fp32 accumulation.
// Per 8 edges: 4× LDG.128 record loads + 8 gather LDG.32 — no tail, no branch.
template <int MODE>
__device__ __forceinline__ void agg_body(const __half2* __restrict__ hin,
                                         __half2* __restrict__ hout_h,
                                         float2* __restrict__ hout_f,
                                         const float2* __restrict__ bias2) {
    int node = blockIdx.x * 8 + (threadIdx.x >> 5);   // 12500*8 == NN exactly
    int lane = threadIdx.x & 31;

    int e = g_rowptr[node];
    int end = g_rowptr[node + 1];

    float d = g_dis[node];
    float2 self = __half22float2(hin[node * 32 + lane]);
    float acx = d * d * self.x;
    float acy = d * d * self.y;
    float bcx = 0.0f, bcy = 0.0f;

    const float4* __restrict__ ed4 = g_edgebuf;

    for (; e < end; e += 8) {
        int p = e >> 1;
        float4 p01 = ed4[p];
        float4 p23 = ed4[p + 1];
        float4 p45 = ed4[p + 2];
        float4 p67 = ed4[p + 3];
        float2 v0 = __half22float2(hin[(size_t)__float_as_int(p01.x) * 32 + lane]);
        float2 v1 = __half22float2(hin[(size_t)__float_as_int(p01.z) * 32 + lane]);
        float2 v2 = __half22float2(hin[(size_t)__float_as_int(p23.x) * 32 + lane]);
        float2 v3 = __half22float2(hin[(size_t)__float_as_int(p23.z) * 32 + lane]);
        float2 v4 = __half22float2(hin[(size_t)__float_as_int(p45.x) * 32 + lane]);
        float2 v5 = __half22float2(hin[(size_t)__float_as_int(p45.z) * 32 + lane]);
        float2 v6 = __half22float2(hin[(size_t)__float_as_int(p67.x) * 32 + lane]);
        float2 v7 = __half22float2(hin[(size_t)__float_as_int(p67.z) * 32 + lane]);
        acx += p01.y * v0.x; acy += p01.y * v0.y;
        bcx += p01.w * v1.x; bcy += p01.w * v1.y;
        acx += p23.y * v2.x; acy += p23.y * v2.y;
        bcx += p23.w * v3.x; bcy += p23.w * v3.y;
        acx += p45.y * v4.x; acy += p45.y * v4.y;
        bcx += p45.w * v5.x; bcy += p45.w * v5.y;
        acx += p67.y * v6.x; acy += p67.y * v6.y;
        bcx += p67.w * v7.x; bcy += p67.w * v7.y;
    }
    acx += bcx;
    acy += bcy;

    if (MODE == 1) {
        float2 b = bias2[lane];
        acx = fmaxf(acx + b.x, 0.0f);
        acy = fmaxf(acy + b.y, 0.0f);
        hout_h[node * 32 + lane] = __floats2half2_rn(acx, acy);
    } else {
        hout_f[node * 32 + lane] = make_float2(acx, acy);
    }
}

__global__ void k_agg1(const float* __restrict__ bias) {
    agg_body<1>(g_ha, g_hb, nullptr, reinterpret_cast<const float2*>(bias));
}

__global__ void k_agg2() {
    agg_body<0>(g_hb, nullptr, reinterpret_cast<float2*>(g_f), nullptr);
}

// ---------------------------------------------------------------------------
// mu = agg2 @ Wmu + bmu ; lv = agg2 @ Wlv + blv  (agg2 fp32 in g_f)
// 256 threads, 64 rows/block, 16 cols/thread.
__global__ void k_gemm2(const float* __restrict__ Wmu, const float* __restrict__ bmu,
                        const float* __restrict__ Wlv, const float* __restrict__ blv,
                        float* __restrict__ out) {
    __shared__ alignas(16) float sW[HID * 64];  // 16 KB: [k][c], c<32=Wmu, c>=32=Wlv
    __shared__ alignas(16) float sA[64 * HID];  // 16 KB, swizzled
    __shared__ alignas(16) float sB[64];
    int tid = threadIdx.x;
    int node0 = blockIdx.x * 64;

    for (int i = tid; i < HID * 64; i += 256) {
        int k = i >> 6, c = i & 63;
        sW[i] = (c < 32) ? Wmu[k * LAT + c] : Wlv[k * LAT + (c - 32)];
    }
    if (tid < 64) sB[tid] = (tid < 32) ? bmu[tid] : blv[tid - 32];
    for (int i = tid; i < 64 * HID; i += 256) {
        int r = i >> 6, k = i & 63;
        int row = node0 + r;
        if (row >= NN) row = NN - 1;               // safe pad (store guarded)
        sA[r * HID + (k ^ (r & 31))] = g_f[(size_t)row * HID + k];
    }
    __syncthreads();

    int r = tid & 63;
    int c0 = (tid >> 6) * 16;
    unsigned long long acc[8] = {0ull, 0ull, 0ull, 0ull, 0ull, 0ull, 0ull, 0ull};

#pragma unroll 4
    for (int k = 0; k < HID; k++) {
        unsigned long long ap = pack2(sA[r * HID + (k ^ (r & 31))]);
        ulonglong2 w0 = *reinterpret_cast<const ulonglong2*>(&sW[k * 64 + c0]);
        ulonglong2 w1 = *reinterpret_cast<const ulonglong2*>(&sW[k * 64 + c0 + 4]);
        ulonglong2 w2 = *reinterpret_cast<const ulonglong2*>(&sW[k * 64 + c0 + 8]);
        ulonglong2 w3 = *reinterpret_cast<const ulonglong2*>(&sW[k * 64 + c0 + 12]);
        ffma2(acc[0], ap, w0.x);
        ffma2(acc[1], ap, w0.y);
        ffma2(acc[2], ap, w1.x);
        ffma2(acc[3], ap, w1.y);
        ffma2(acc[4], ap, w2.x);
        ffma2(acc[5], ap, w2.y);
        ffma2(acc[6], ap, w3.x);
        ffma2(acc[7], ap, w3.y);
    }

    int node = node0 + r;
    if (node >= NN) return;
    float o[16];
#pragma unroll
    for (int j = 0; j < 8; j++) unpack2(acc[j], o[2 * j], o[2 * j + 1]);
#pragma unroll
    for (int j = 0; j < 16; j++) {
        int c = c0 + j;
        float v = o[j] + sB[c];
        if (c < 32)
            out[(size_t)node * LAT + c] = v;                            // mu
        else
            out[(size_t)NN * LAT + (size_t)node * LAT + (c - 32)] = v;  // logvar
    }
}

// ---------------------------------------------------------------------------
extern "C" void kernel_launch(void* const* d_in, const int* in_sizes, int n_in,
                              void* d_out, int out_size) {
    const float* x    = (const float*)d_in[0];
    const int*   ei   = (const int*)d_in[1];    // int32 or int64 (detected)
    const float* W1   = (const float*)d_in[2];
    const float* b1   = (const float*)d_in[3];
    const float* Wmu  = (const float*)d_in[4];
    const float* bmu  = (const float*)d_in[5];
    const float* Wlv  = (const float*)d_in[6];
    const float* blv  = (const float*)d_in[7];
    float*       out  = (float*)d_out;

    // CSR build (padded segments)
    k_zero_detect<<<(NN + 255) / 256, 256>>>(ei);
    k_count_deg<<<(NE + 255) / 256, 256>>>(ei);
    k_scan_local<<<SCAN_NB, SCAN_BLK>>>();
    k_finalize_csr<<<(NN + 255) / 256, 256>>>();
    k_scatter<<<(NE + 255) / 256, 256>>>(ei);

    // Dense + propagate
    k_gemm1<<<(NN + 63) / 64, 256>>>(x, W1);          // g_ha = fp16(x@W1)
    k_agg1<<<NN / 8, 256>>>(b1);                      // g_hb = fp16(relu(P ha + b1))
    k_agg2<<<NN / 8, 256>>>();                        // g_f  = P hb (fp32)
    k_gemm2<<<(NN + 63) / 64, 256>>>(Wmu, bmu, Wlv, blv, out);
}

// round 10
// speedup vs baseline: 1.0278x; 1.0278x over previous
#include <cuda_runtime.h>
#include <cuda_fp16.h>

#define NN 100000
#define NE 1600000
#define IN_CH 128
#define HID 64
#define LAT 32

#define SCAN_BLK 512
#define SCAN_NB ((NN + SCAN_BLK - 1) / SCAN_BLK)   // 196
#define NEP (NE + 8 * NN)                          // padded edge capacity

// Scratch (static __device__ — no allocations allowed)
__device__ int     g_stride;              // 1 = edge_index int32, 2 = int64
__device__ int     g_deg[NN];
__device__ int     g_rowptr[NN + 1];      // padded CSR offsets (multiples of 8)
__device__ int     g_cursor[NN];
__device__ int     g_blocksums[SCAN_NB];
__device__ int     g_srcbuf[NEP];         // per-edge source index (pad = NN)
__device__ float   g_dis[NN];
__device__ __half2 g_ha[(NN + 1) * 32];   // dis*h1 fp16; ghost node NN stays 0
__device__ __half2 g_hb[(NN + 1) * 32];   // dis*relu(...) fp16; ghost stays 0
__device__ float   g_f[NN * HID];         // agg2 output fp32 (gemm2 input)

struct alignas(16) H8 { __half2 h[4]; };

// ---------------------------------------------------------------------------
__device__ __forceinline__ void ffma2(unsigned long long& acc,
                                      unsigned long long a,
                                      unsigned long long b) {
    asm("fma.rn.f32x2 %0, %1, %2, %0;" : "+l"(acc) : "l"(a), "l"(b));
}
__device__ __forceinline__ unsigned long long pack2(float v) {
    unsigned long long r;
    asm("mov.b64 %0, {%1, %1};" : "=l"(r) : "f"(v));
    return r;
}
__device__ __forceinline__ void unpack2(unsigned long long p, float& lo, float& hi) {
    asm("mov.b64 {%0, %1}, %2;" : "=f"(lo), "=f"(hi) : "l"(p));
}

// ---------------------------------------------------------------------------
// Zero degrees; block 0 warp 0 detects edge_index dtype (int64 → odd words 0).
__global__ void k_zero_detect(const int* __restrict__ ei) {
    int i = blockIdx.x * blockDim.x + threadIdx.x;
    if (i < NN) g_deg[i] = 0;
    if (blockIdx.x == 0 && threadIdx.x < 32) {
        int lane = threadIdx.x;
        int v = ei[2 * lane + 1];
        unsigned m = __ballot_sync(0xffffffffu, v != 0);
        if (lane == 0) g_stride = (m == 0u) ? 2 : 1;
    }
}

__global__ void k_count_deg(const int* __restrict__ ei) {
    int e = blockIdx.x * blockDim.x + threadIdx.x;
    if (e >= NE) return;
    int st = g_stride;
    int c = ei[(size_t)st * NE + (size_t)e * st];   // target node
    atomicAdd(&g_deg[c], 1);
}

// Per-block exclusive scan of PADDED degrees -> g_rowptr (local part).
// Also computes dis = rsqrt(deg+1) so gemm1 can run right after this.
__global__ void k_scan_local() {
    __shared__ int s[SCAN_BLK];
    int t = threadIdx.x;
    int i = blockIdx.x * SCAN_BLK + t;
    int deg = (i < NN) ? g_deg[i] : 0;
    if (i < NN) g_dis[i] = rsqrtf((float)deg + 1.0f);
    int v = (deg + 7) & ~7;                          // pad to multiple of 8
    s[t] = v;
    __syncthreads();
#pragma unroll
    for (int off = 1; off < SCAN_BLK; off <<= 1) {
        int add = (t >= off) ? s[t - off] : 0;
        __syncthreads();
        s[t] += add;
        __syncthreads();
    }
    if (i < NN) g_rowptr[i] = s[t] - v;   // exclusive (local)
    if (t == SCAN_BLK - 1) g_blocksums[blockIdx.x] = s[t];
}

// ---------------------------------------------------------------------------
// h1 = x @ W1; output ĥ = fp16(dis * h1) to g_ha.
// 256 threads; 128 rows/block in FOUR 32-row phases sharing one W load.
__global__ void k_gemm1(const float* __restrict__ x, const float* __restrict__ W) {
    __shared__ alignas(16) float sW[IN_CH * HID];   // 32 KB, [k][c]
    __shared__ alignas(16) float sX[32 * IN_CH];    // 16 KB, swizzled [r][k^r]
    int tid = threadIdx.x;
    int base0 = blockIdx.x * 128;

    for (int i = tid; i < IN_CH * HID; i += 256) sW[i] = W[i];

    int r = tid & 31;
    int c0 = (tid >> 5) * 8;

#pragma unroll
    for (int phase = 0; phase < 4; phase++) {
        int node0 = base0 + phase * 32;
        __syncthreads();   // sW ready / previous phase compute done
        for (int i = tid; i < 32 * IN_CH; i += 256) {
            int rr = i >> 7, k = i & 127;
            int row = node0 + rr;
            if (row >= NN) row = NN - 1;            // safe pad (store guarded)
            sX[rr * IN_CH + (k ^ rr)] = x[(size_t)row * IN_CH + k];
        }
        __syncthreads();

        unsigned long long acc[4] = {0ull, 0ull, 0ull, 0ull};
#pragma unroll 4
        for (int k = 0; k < IN_CH; k++) {
            unsigned long long xp = pack2(sX[r * IN_CH + (k ^ r)]);
            ulonglong2 w0 = *reinterpret_cast<const ulonglong2*>(&sW[k * HID + c0]);
            ulonglong2 w1 = *reinterpret_cast<const ulonglong2*>(&sW[k * HID + c0 + 4]);
            ffma2(acc[0], xp, w0.x);
            ffma2(acc[1], xp, w0.y);
            ffma2(acc[2], xp, w1.x);
            ffma2(acc[3], xp, w1.y);
        }

        int node = node0 + r;
        if (node < NN) {
            float d = g_dis[node];
            float o[8];
#pragma unroll
            for (int j = 0; j < 4; j++) unpack2(acc[j], o[2 * j], o[2 * j + 1]);
            H8 v;
#pragma unroll
            for (int j = 0; j < 4; j++)
                v.h[j] = __floats2half2_rn(d * o[2 * j], d * o[2 * j + 1]);
            *reinterpret_cast<H8*>(&g_ha[(size_t)node * 32 + (c0 >> 1)]) = v;
        }
    }
}

// Finalize: every block redundantly scans the 196 block sums in smem, then
// rowptr += prefix; cursor = rowptr; pad slots get ghost source NN.
__global__ void k_finalize_csr() {
    __shared__ int s[256];
    int t = threadIdx.x;
    int bv = (t < SCAN_NB) ? g_blocksums[t] : 0;
    s[t] = bv;
    __syncthreads();
#pragma unroll
    for (int off = 1; off < 256; off <<= 1) {
        int add = (t >= off) ? s[t - off] : 0;
        __syncthreads();
        s[t] += add;
        __syncthreads();
    }
    // s[k] is the INCLUSIVE prefix of blocksums.
    int i = blockIdx.x * blockDim.x + t;
    if (i < NN) {
        int sb = i >> 9;
        int prefix = (sb > 0) ? s[sb - 1] : 0;
        int rp = g_rowptr[i] + prefix;
        g_rowptr[i] = rp;
        g_cursor[i] = rp;
        int deg = g_deg[i];
        int pdeg = (deg + 7) & ~7;
        for (int j = rp + deg; j < rp + pdeg; j++)
            g_srcbuf[j] = NN;                        // ghost node: features 0
    }
    if (i == 0) g_rowptr[NN] = s[SCAN_NB - 1];
}

// Scatter edge sources into destination-sorted padded order (4B records).
__global__ void k_scatter(const int* __restrict__ ei) {
    int e = blockIdx.x * blockDim.x + threadIdx.x;
    if (e >= NE) return;
    int st = g_stride;
    int r = ei[(size_t)e * st];                     // source
    int c = ei[(size_t)st * NE + (size_t)e * st];   // target
    int pos = atomicAdd(&g_cursor[c], 1);
    g_srcbuf[pos] = r;
}

// ---------------------------------------------------------------------------
// CSR aggregation over PADDED segments (exact multiples of 8 edges).
// WARP per node: 32 lanes × half2 = 64 channels; fp32 accumulation.
// in is pre-scaled ĥ = dis*h, so: out = dis[dst] * (Σ ĥ[src] + ĥ[dst]).
// Per 8 edges: 2× LDG.128 record loads + 8 gather LDG.64 + pure adds.
template <int MODE>
__device__ __forceinline__ void agg_body(const __half2* __restrict__ hin,
                                         __half2* __restrict__ hout_h,
                                         float2* __restrict__ hout_f,
                                         const float2* __restrict__ bias2) {
    int node = blockIdx.x * 8 + (threadIdx.x >> 5);   // 12500*8 == NN exactly
    int lane = threadIdx.x & 31;

    int e = g_rowptr[node];
    int end = g_rowptr[node + 1];

    float2 self = __half22float2(hin[(size_t)node * 32 + lane]);
    float acx = self.x, acy = self.y;
    float bcx = 0.0f, bcy = 0.0f;

    const int* __restrict__ sp = g_srcbuf;

    for (; e < end; e += 8) {
        int4 a = *reinterpret_cast<const int4*>(sp + e);
        int4 b = *reinterpret_cast<const int4*>(sp + e + 4);
        float2 v0 = __half22float2(hin[(size_t)a.x * 32 + lane]);
        float2 v1 = __half22float2(hin[(size_t)a.y * 32 + lane]);
        float2 v2 = __half22float2(hin[(size_t)a.z * 32 + lane]);
        float2 v3 = __half22float2(hin[(size_t)a.w * 32 + lane]);
        float2 v4 = __half22float2(hin[(size_t)b.x * 32 + lane]);
        float2 v5 = __half22float2(hin[(size_t)b.y * 32 + lane]);
        float2 v6 = __half22float2(hin[(size_t)b.z * 32 + lane]);
        float2 v7 = __half22float2(hin[(size_t)b.w * 32 + lane]);
        acx += v0.x; acy += v0.y;
        bcx += v1.x; bcy += v1.y;
        acx += v2.x; acy += v2.y;
        bcx += v3.x; bcy += v3.y;
        acx += v4.x; acy += v4.y;
        bcx += v5.x; bcy += v5.y;
        acx += v6.x; acy += v6.y;
        bcx += v7.x; bcy += v7.y;
    }
    float d = g_dis[node];
    acx = d * (acx + bcx);
    acy = d * (acy + bcy);

    if (MODE == 1) {
        float2 b = bias2[lane];
        float hx = fmaxf(acx + b.x, 0.0f);
        float hy = fmaxf(acy + b.y, 0.0f);
        hout_h[(size_t)node * 32 + lane] = __floats2half2_rn(d * hx, d * hy);
    } else {
        hout_f[(size_t)node * 32 + lane] = make_float2(acx, acy);
    }
}

__global__ void k_agg1(const float* __restrict__ bias) {
    agg_body<1>(g_ha, g_hb, nullptr, reinterpret_cast<const float2*>(bias));
}

__global__ void k_agg2() {
    agg_body<0>(g_hb, nullptr, reinterpret_cast<float2*>(g_f), nullptr);
}

// ---------------------------------------------------------------------------
// mu = agg2 @ Wmu + bmu ; lv = agg2 @ Wlv + blv  (agg2 fp32 in g_f)
// 256 threads; 128 rows/block in TWO 64-row phases sharing one W load.
__global__ void k_gemm2(const float* __restrict__ Wmu, const float* __restrict__ bmu,
                        const float* __restrict__ Wlv, const float* __restrict__ blv,
                        float* __restrict__ out) {
    __shared__ alignas(16) float sW[HID * 64];  // 16 KB: [k][c], c<32=Wmu else Wlv
    __shared__ alignas(16) float sA[64 * HID];  // 16 KB, swizzled
    __shared__ alignas(16) float sB[64];
    int tid = threadIdx.x;
    int base0 = blockIdx.x * 128;

    for (int i = tid; i < HID * 64; i += 256) {
        int k = i >> 6, c = i & 63;
        sW[i] = (c < 32) ? Wmu[k * LAT + c] : Wlv[k * LAT + (c - 32)];
    }
    if (tid < 64) sB[tid] = (tid < 32) ? bmu[tid] : blv[tid - 32];

    int r = tid & 63;
    int c0 = (tid >> 6) * 16;

#pragma unroll
    for (int phase = 0; phase < 2; phase++) {
        int node0 = base0 + phase * 64;
        __syncthreads();
        for (int i = tid; i < 64 * HID; i += 256) {
            int rr = i >> 6, k = i & 63;
            int row = node0 + rr;
            if (row >= NN) row = NN - 1;            // safe pad (store guarded)
            sA[rr * HID + (k ^ (rr & 31))] = g_f[(size_t)row * HID + k];
        }
        __syncthreads();

        unsigned long long acc[8] = {0ull,0ull,0ull,0ull,0ull,0ull,0ull,0ull};
#pragma unroll 4
        for (int k = 0; k < HID; k++) {
            unsigned long long ap = pack2(sA[r * HID + (k ^ (r & 31))]);
            ulonglong2 w0 = *reinterpret_cast<const ulonglong2*>(&sW[k * 64 + c0]);
            ulonglong2 w1 = *reinterpret_cast<const ulonglong2*>(&sW[k * 64 + c0 + 4]);
            ulonglong2 w2 = *reinterpret_cast<const ulonglong2*>(&sW[k * 64 + c0 + 8]);
            ulonglong2 w3 = *reinterpret_cast<const ulonglong2*>(&sW[k * 64 + c0 + 12]);
            ffma2(acc[0], ap, w0.x);
            ffma2(acc[1], ap, w0.y);
            ffma2(acc[2], ap, w1.x);
            ffma2(acc[3], ap, w1.y);
            ffma2(acc[4], ap, w2.x);
            ffma2(acc[5], ap, w2.y);
            ffma2(acc[6], ap, w3.x);
            ffma2(acc[7], ap, w3.y);
        }

        int node = node0 + r;
        if (node < NN) {
            float o[16];
#pragma unroll
            for (int j = 0; j < 8; j++) unpack2(acc[j], o[2 * j], o[2 * j + 1]);
#pragma unroll
            for (int j = 0; j < 16; j++) {
                int c = c0 + j;
                float v = o[j] + sB[c];
                if (c < 32)
                    out[(size_t)node * LAT + c] = v;                            // mu
                else
                    out[(size_t)NN * LAT + (size_t)node * LAT + (c - 32)] = v;  // lv
            }
        }
    }
}

// ---------------------------------------------------------------------------
extern "C" void kernel_launch(void* const* d_in, const int* in_sizes, int n_in,
                              void* d_out, int out_size) {
    const float* x    = (const float*)d_in[0];
    const int*   ei   = (const int*)d_in[1];    // int32 or int64 (detected)
    const float* W1   = (const float*)d_in[2];
    const float* b1   = (const float*)d_in[3];
    const float* Wmu  = (const float*)d_in[4];
    const float* bmu  = (const float*)d_in[5];
    const float* Wlv  = (const float*)d_in[6];
    const float* blv  = (const float*)d_in[7];
    float*       out  = (float*)d_out;

    k_zero_detect<<<(NN + 255) / 256, 256>>>(ei);       // 1
    k_count_deg<<<(NE + 255) / 256, 256>>>(ei);         // 2
    k_scan_local<<<SCAN_NB, SCAN_BLK>>>();              // 3 (also dis)
    k_gemm1<<<(NN + 127) / 128, 256>>>(x, W1);          // 4 ← ncu profiles this
    k_finalize_csr<<<(NN + 255) / 256, 256>>>();        // 5
    k_scatter<<<(NE + 255) / 256, 256>>>(ei);           // 6
    k_agg1<<<NN / 8, 256>>>(b1);                        // 7
    k_agg2<<<NN / 8, 256>>>();                          // 8
    k_gemm2<<<(NN + 127) / 128, 256>>>(Wmu, bmu, Wlv, blv, out);  // 9
}

// round 11
// speedup vs baseline: 1.2435x; 1.2099x over previous
#include <cuda_runtime.h>
#include <cuda_fp16.h>

#define NN 100000
#define NE 1600000
#define IN_CH 128
#define HID 64
#define LAT 32

#define SCAN_BLK 512
#define SCAN_NB ((NN + SCAN_BLK - 1) / SCAN_BLK)   // 196
#define NEP (NE + 8 * NN)                          // padded edge capacity

// Scratch (static __device__ — no allocations allowed)
__device__ int     g_stride;              // 1 = edge_index int32, 2 = int64
__device__ int     g_deg[NN];
__device__ int     g_rowptr[NN + 1];      // padded CSR offsets (multiples of 8)
__device__ int     g_cursor[NN];
__device__ int     g_blocksums[SCAN_NB];
__device__ int     g_srcbuf[NEP];         // per-edge source index (pad = NN)
__device__ float   g_dis[NN];
__device__ __half2 g_ha[(NN + 1) * 32];   // dis*h1 fp16; ghost node NN stays 0
__device__ __half2 g_hb[(NN + 1) * 32];   // dis*relu(...) fp16; ghost stays 0
__device__ float   g_f[NN * HID];         // agg2 output fp32 (gemm2 input)

struct alignas(16) H8 { __half2 h[4]; };

// ---------------------------------------------------------------------------
__device__ __forceinline__ void ffma2(unsigned long long& acc,
                                      unsigned long long a,
                                      unsigned long long b) {
    asm("fma.rn.f32x2 %0, %1, %2, %0;" : "+l"(acc) : "l"(a), "l"(b));
}
__device__ __forceinline__ unsigned long long pack2(float v) {
    unsigned long long r;
    asm("mov.b64 %0, {%1, %1};" : "=l"(r) : "f"(v));
    return r;
}
__device__ __forceinline__ void unpack2(unsigned long long p, float& lo, float& hi) {
    asm("mov.b64 {%0, %1}, %2;" : "=f"(lo), "=f"(hi) : "l"(p));
}

// ---------------------------------------------------------------------------
// Zero degrees; block 0 warp 0 detects edge_index dtype (int64 → odd words 0).
__global__ void k_zero_detect(const int* __restrict__ ei) {
    int i = blockIdx.x * blockDim.x + threadIdx.x;
    if (i < NN) g_deg[i] = 0;
    if (blockIdx.x == 0 && threadIdx.x < 32) {
        int lane = threadIdx.x;
        int v = ei[2 * lane + 1];
        unsigned m = __ballot_sync(0xffffffffu, v != 0);
        if (lane == 0) g_stride = (m == 0u) ? 2 : 1;
    }
}

__global__ void k_count_deg(const int* __restrict__ ei) {
    int e = blockIdx.x * blockDim.x + threadIdx.x;
    if (e >= NE) return;
    int st = g_stride;
    int c = ei[(size_t)st * NE + (size_t)e * st];   // target node
    atomicAdd(&g_deg[c], 1);
}

// Per-block exclusive scan of PADDED degrees -> g_rowptr (local part).
// Also computes dis = rsqrt(deg+1) so gemm1 can run right after this.
__global__ void k_scan_local() {
    __shared__ int s[SCAN_BLK];
    int t = threadIdx.x;
    int i = blockIdx.x * SCAN_BLK + t;
    int deg = (i < NN) ? g_deg[i] : 0;
    if (i < NN) g_dis[i] = rsqrtf((float)deg + 1.0f);
    int v = (deg + 7) & ~7;                          // pad to multiple of 8
    s[t] = v;
    __syncthreads();
#pragma unroll
    for (int off = 1; off < SCAN_BLK; off <<= 1) {
        int add = (t >= off) ? s[t - off] : 0;
        __syncthreads();
        s[t] += add;
        __syncthreads();
    }
    if (i < NN) g_rowptr[i] = s[t] - v;   // exclusive (local)
    if (t == SCAN_BLK - 1) g_blocksums[blockIdx.x] = s[t];
}

// ---------------------------------------------------------------------------
// h1 = x @ W1; output ĥ = fp16(dis * h1) to g_ha.
// 256 threads, 128 rows/block. Register blocking: 4 rows × 8 cols per thread.
// sXt is k-transposed so one LDS.128 yields 4 row values; sW broadcast.
__global__ void k_gemm1(const float* __restrict__ x, const float* __restrict__ W) {
    __shared__ alignas(16) float sW[IN_CH * HID];    // 32 KB, [k][c]
    __shared__ alignas(16) float sXt[32 * 128];      // 16 KB, [k_local][row]
    int tid = threadIdx.x;
    int base0 = blockIdx.x * 128;

    for (int i = tid; i < IN_CH * HID; i += 256) sW[i] = W[i];

    int lane = tid & 31;
    int c0 = (tid >> 5) * 8;          // warp → 8 columns
    int lrow = tid & 127;             // loader: row within tile
    int kg = tid >> 7;                // loader: which 16-k group
    int grow = base0 + lrow;
    if (grow >= NN) grow = NN - 1;    // safe pad (stores guarded)
    const float4* xrow = reinterpret_cast<const float4*>(x + (size_t)grow * IN_CH);

    unsigned long long acc[16];       // [row j][col-pair p] = acc[j*4+p]
#pragma unroll
    for (int i = 0; i < 16; i++) acc[i] = 0ull;

    for (int kc = 0; kc < IN_CH; kc += 32) {
        __syncthreads();
        // Load x[*, kc..kc+32) transposed: 16 k-values per thread.
        {
            int k0 = kg * 16;
#pragma unroll
            for (int q = 0; q < 4; q++) {
                float4 v = xrow[(kc + k0) / 4 + q];
                sXt[(k0 + 4 * q + 0) * 128 + lrow] = v.x;
                sXt[(k0 + 4 * q + 1) * 128 + lrow] = v.y;
                sXt[(k0 + 4 * q + 2) * 128 + lrow] = v.z;
                sXt[(k0 + 4 * q + 3) * 128 + lrow] = v.w;
            }
        }
        __syncthreads();

#pragma unroll
        for (int k = 0; k < 32; k++) {
            float4 rv = *reinterpret_cast<const float4*>(&sXt[k * 128 + 4 * lane]);
            unsigned long long xp0 = pack2(rv.x);
            unsigned long long xp1 = pack2(rv.y);
            unsigned long long xp2 = pack2(rv.z);
            unsigned long long xp3 = pack2(rv.w);
            ulonglong2 w0 = *reinterpret_cast<const ulonglong2*>(&sW[(kc + k) * HID + c0]);
            ulonglong2 w1 = *reinterpret_cast<const ulonglong2*>(&sW[(kc + k) * HID + c0 + 4]);
            ffma2(acc[0],  xp0, w0.x); ffma2(acc[1],  xp0, w0.y);
            ffma2(acc[2],  xp0, w1.x); ffma2(acc[3],  xp0, w1.y);
            ffma2(acc[4],  xp1, w0.x); ffma2(acc[5],  xp1, w0.y);
            ffma2(acc[6],  xp1, w1.x); ffma2(acc[7],  xp1, w1.y);
            ffma2(acc[8],  xp2, w0.x); ffma2(acc[9],  xp2, w0.y);
            ffma2(acc[10], xp2, w1.x); ffma2(acc[11], xp2, w1.y);
            ffma2(acc[12], xp3, w0.x); ffma2(acc[13], xp3, w0.y);
            ffma2(acc[14], xp3, w1.x); ffma2(acc[15], xp3, w1.y);
        }
    }

#pragma unroll
    for (int j = 0; j < 4; j++) {
        int node = base0 + 4 * lane + j;
        if (node < NN) {
            float d = g_dis[node];
            float o[8];
#pragma unroll
            for (int p = 0; p < 4; p++) unpack2(acc[j * 4 + p], o[2 * p], o[2 * p + 1]);
            H8 v;
#pragma unroll
            for (int p = 0; p < 4; p++)
                v.h[p] = __floats2half2_rn(d * o[2 * p], d * o[2 * p + 1]);
            *reinterpret_cast<H8*>(&g_ha[(size_t)node * 32 + (c0 >> 1)]) = v;
        }
    }
}

// Finalize: every block redundantly scans the 196 block sums in smem, then
// rowptr += prefix; cursor = rowptr; pad slots get ghost source NN.
__global__ void k_finalize_csr() {
    __shared__ int s[256];
    int t = threadIdx.x;
    int bv = (t < SCAN_NB) ? g_blocksums[t] : 0;
    s[t] = bv;
    __syncthreads();
#pragma unroll
    for (int off = 1; off < 256; off <<= 1) {
        int add = (t >= off) ? s[t - off] : 0;
        __syncthreads();
        s[t] += add;
        __syncthreads();
    }
    int i = blockIdx.x * blockDim.x + t;
    if (i < NN) {
        int sb = i >> 9;
        int prefix = (sb > 0) ? s[sb - 1] : 0;
        int rp = g_rowptr[i] + prefix;
        g_rowptr[i] = rp;
        g_cursor[i] = rp;
        int deg = g_deg[i];
        int pdeg = (deg + 7) & ~7;
        for (int j = rp + deg; j < rp + pdeg; j++)
            g_srcbuf[j] = NN;                        // ghost node: features 0
    }
    if (i == 0) g_rowptr[NN] = s[SCAN_NB - 1];
}

// Scatter edge sources into destination-sorted padded order (4B records).
__global__ void k_scatter(const int* __restrict__ ei) {
    int e = blockIdx.x * blockDim.x + threadIdx.x;
    if (e >= NE) return;
    int st = g_stride;
    int r = ei[(size_t)e * st];                     // source
    int c = ei[(size_t)st * NE + (size_t)e * st];   // target
    int pos = atomicAdd(&g_cursor[c], 1);
    g_srcbuf[pos] = r;
}

// ---------------------------------------------------------------------------
// CSR aggregation over PADDED segments (exact multiples of 8 edges).
// WARP per node: 32 lanes × half2 = 64 channels; fp32 accumulation.
// in is pre-scaled ĥ = dis*h, so: out = dis[dst] * (Σ ĥ[src] + ĥ[dst]).
template <int MODE>
__device__ __forceinline__ void agg_body(const __half2* __restrict__ hin,
                                         __half2* __restrict__ hout_h,
                                         float2* __restrict__ hout_f,
                                         const float2* __restrict__ bias2) {
    int node = blockIdx.x * 8 + (threadIdx.x >> 5);   // 12500*8 == NN exactly
    int lane = threadIdx.x & 31;

    int e = g_rowptr[node];
    int end = g_rowptr[node + 1];

    float2 self = __half22float2(hin[(size_t)node * 32 + lane]);
    float acx = self.x, acy = self.y;
    float bcx = 0.0f, bcy = 0.0f;

    const int* __restrict__ sp = g_srcbuf;

    for (; e < end; e += 8) {
        int4 a = *reinterpret_cast<const int4*>(sp + e);
        int4 b = *reinterpret_cast<const int4*>(sp + e + 4);
        float2 v0 = __half22float2(hin[(size_t)a.x * 32 + lane]);
        float2 v1 = __half22float2(hin[(size_t)a.y * 32 + lane]);
        float2 v2 = __half22float2(hin[(size_t)a.z * 32 + lane]);
        float2 v3 = __half22float2(hin[(size_t)a.w * 32 + lane]);
        float2 v4 = __half22float2(hin[(size_t)b.x * 32 + lane]);
        float2 v5 = __half22float2(hin[(size_t)b.y * 32 + lane]);
        float2 v6 = __half22float2(hin[(size_t)b.z * 32 + lane]);
        float2 v7 = __half22float2(hin[(size_t)b.w * 32 + lane]);
        acx += v0.x; acy += v0.y;
        bcx += v1.x; bcy += v1.y;
        acx += v2.x; acy += v2.y;
        bcx += v3.x; bcy += v3.y;
        acx += v4.x; acy += v4.y;
        bcx += v5.x; bcy += v5.y;
        acx += v6.x; acy += v6.y;
        bcx += v7.x; bcy += v7.y;
    }
    float d = g_dis[node];
    acx = d * (acx + bcx);
    acy = d * (acy + bcy);

    if (MODE == 1) {
        float2 b = bias2[lane];
        float hx = fmaxf(acx + b.x, 0.0f);
        float hy = fmaxf(acy + b.y, 0.0f);
        hout_h[(size_t)node * 32 + lane] = __floats2half2_rn(d * hx, d * hy);
    } else {
        hout_f[(size_t)node * 32 + lane] = make_float2(acx, acy);
    }
}

__global__ void k_agg1(const float* __restrict__ bias) {
    agg_body<1>(g_ha, g_hb, nullptr, reinterpret_cast<const float2*>(bias));
}

__global__ void k_agg2() {
    agg_body<0>(g_hb, nullptr, reinterpret_cast<float2*>(g_f), nullptr);
}

// ---------------------------------------------------------------------------
// mu/lv = agg2 @ [Wmu|Wlv] + [bmu|blv]. Same register-blocked scheme:
// 4 rows × 8 cols per thread, 128 rows/block, k chunks of 32 (2 chunks).
__global__ void k_gemm2(const float* __restrict__ Wmu, const float* __restrict__ bmu,
                        const float* __restrict__ Wlv, const float* __restrict__ blv,
                        float* __restrict__ out) {
    __shared__ alignas(16) float sW[HID * 64];       // 16 KB: [k][c]
    __shared__ alignas(16) float sAt[32 * 128];      // 16 KB, [k_local][row]
    __shared__ alignas(16) float sB[64];
    int tid = threadIdx.x;
    int base0 = blockIdx.x * 128;

    for (int i = tid; i < HID * 64; i += 256) {
        int k = i >> 6, c = i & 63;
        sW[i] = (c < 32) ? Wmu[k * LAT + c] : Wlv[k * LAT + (c - 32)];
    }
    if (tid < 64) sB[tid] = (tid < 32) ? bmu[tid] : blv[tid - 32];

    int lane = tid & 31;
    int c0 = (tid >> 5) * 8;
    int lrow = tid & 127;
    int kg = tid >> 7;
    int grow = base0 + lrow;
    if (grow >= NN) grow = NN - 1;
    const float4* arow = reinterpret_cast<const float4*>(g_f + (size_t)grow * HID);

    unsigned long long acc[16];
#pragma unroll
    for (int i = 0; i < 16; i++) acc[i] = 0ull;

    for (int kc = 0; kc < HID; kc += 32) {
        __syncthreads();
        {
            int k0 = kg * 16;
#pragma unroll
            for (int q = 0; q < 4; q++) {
                float4 v = arow[(kc + k0) / 4 + q];
                sAt[(k0 + 4 * q + 0) * 128 + lrow] = v.x;
                sAt[(k0 + 4 * q + 1) * 128 + lrow] = v.y;
                sAt[(k0 + 4 * q + 2) * 128 + lrow] = v.z;
                sAt[(k0 + 4 * q + 3) * 128 + lrow] = v.w;
            }
        }
        __syncthreads();

#pragma unroll
        for (int k = 0; k < 32; k++) {
            float4 rv = *reinterpret_cast<const float4*>(&sAt[k * 128 + 4 * lane]);
            unsigned long long xp0 = pack2(rv.x);
            unsigned long long xp1 = pack2(rv.y);
            unsigned long long xp2 = pack2(rv.z);
            unsigned long long xp3 = pack2(rv.w);
            ulonglong2 w0 = *reinterpret_cast<const ulonglong2*>(&sW[(kc + k) * 64 + c0]);
            ulonglong2 w1 = *reinterpret_cast<const ulonglong2*>(&sW[(kc + k) * 64 + c0 + 4]);
            ffma2(acc[0],  xp0, w0.x); ffma2(acc[1],  xp0, w0.y);
            ffma2(acc[2],  xp0, w1.x); ffma2(acc[3],  xp0, w1.y);
            ffma2(acc[4],  xp1, w0.x); ffma2(acc[5],  xp1, w0.y);
            ffma2(acc[6],  xp1, w1.x); ffma2(acc[7],  xp1, w1.y);
            ffma2(acc[8],  xp2, w0.x); ffma2(acc[9],  xp2, w0.y);
            ffma2(acc[10], xp2, w1.x); ffma2(acc[11], xp2, w1.y);
            ffma2(acc[12], xp3, w0.x); ffma2(acc[13], xp3, w0.y);
            ffma2(acc[14], xp3, w1.x); ffma2(acc[15], xp3, w1.y);
        }
    }

#pragma unroll
    for (int j = 0; j < 4; j++) {
        int node = base0 + 4 * lane + j;
        if (node < NN) {
            float o[8];
#pragma unroll
            for (int p = 0; p < 4; p++) unpack2(acc[j * 4 + p], o[2 * p], o[2 * p + 1]);
#pragma unroll
            for (int p = 0; p < 8; p++) {
                int c = c0 + p;
                float v = o[p] + sB[c];
                if (c < 32)
                    out[(size_t)node * LAT + c] = v;                            // mu
                else
                    out[(size_t)NN * LAT + (size_t)node * LAT + (c - 32)] = v;  // lv
            }
        }
    }
}

// ---------------------------------------------------------------------------
extern "C" void kernel_launch(void* const* d_in, const int* in_sizes, int n_in,
                              void* d_out, int out_size) {
    const float* x    = (const float*)d_in[0];
    const int*   ei   = (const int*)d_in[1];    // int32 or int64 (detected)
    const float* W1   = (const float*)d_in[2];
    const float* b1   = (const float*)d_in[3];
    const float* Wmu  = (const float*)d_in[4];
    const float* bmu  = (const float*)d_in[5];
    const float* Wlv  = (const float*)d_in[6];
    const float* blv  = (const float*)d_in[7];
    float*       out  = (float*)d_out;

    k_zero_detect<<<(NN + 255) / 256, 256>>>(ei);       // 1
    k_count_deg<<<(NE + 255) / 256, 256>>>(ei);         // 2
    k_scan_local<<<SCAN_NB, SCAN_BLK>>>();              // 3 (also dis)
    k_gemm1<<<(NN + 127) / 128, 256>>>(x, W1);          // 4 ← ncu profiles this
    k_finalize_csr<<<(NN + 255) / 256, 256>>>();        // 5
    k_scatter<<<(NE + 255) / 256, 256>>>(ei);           // 6
    k_agg1<<<NN / 8, 256>>>(b1);                        // 7
    k_agg2<<<NN / 8, 256>>>();                          // 8
    k_gemm2<<<(NN + 127) / 128, 256>>>(Wmu, bmu, Wlv, blv, out);  // 9
}

// round 12
// speedup vs baseline: 1.2437x; 1.0001x over previous
#include <cuda_runtime.h>
#include <cuda_fp16.h>

#define NN 100000
#define NE 1600000
#define IN_CH 128
#define HID 64
#define LAT 32

#define SCAN_BLK 512
#define SCAN_NB ((NN + SCAN_BLK - 1) / SCAN_BLK)   // 196
#define NEP (NE + 8 * NN)                          // padded edge capacity

// Scratch (static __device__ — no allocations allowed)
__device__ int     g_stride;              // 1 = edge_index int32, 2 = int64
__device__ int     g_deg[NN];
__device__ int     g_rowptr[NN + 1];      // padded CSR offsets (multiples of 8)
__device__ int     g_cursor[NN];
__device__ int     g_blocksums[SCAN_NB];
__device__ int     g_srcbuf[NEP];         // per-edge source index (pad = NN)
__device__ float   g_dis[NN];
__device__ __half2 g_ha[(NN + 1) * 32];   // dis*h1 fp16; ghost node NN stays 0
__device__ __half2 g_hb[(NN + 1) * 32];   // dis*relu(...) fp16; ghost stays 0
__device__ float   g_f[NN * HID];         // agg2 output fp32 (gemm2 input)

struct alignas(16) H8 { __half2 h[4]; };

// ---------------------------------------------------------------------------
__device__ __forceinline__ void ffma2(unsigned long long& acc,
                                      unsigned long long a,
                                      unsigned long long b) {
    asm("fma.rn.f32x2 %0, %1, %2, %0;" : "+l"(acc) : "l"(a), "l"(b));
}
__device__ __forceinline__ unsigned long long pack2(float v) {
    unsigned long long r;
    asm("mov.b64 %0, {%1, %1};" : "=l"(r) : "f"(v));
    return r;
}
__device__ __forceinline__ void unpack2(unsigned long long p, float& lo, float& hi) {
    asm("mov.b64 {%0, %1}, %2;" : "=f"(lo), "=f"(hi) : "l"(p));
}

// ---------------------------------------------------------------------------
// Zero degrees; block 0 warp 0 detects edge_index dtype (int64 → odd words 0).
__global__ void k_zero_detect(const int* __restrict__ ei) {
    int i = blockIdx.x * blockDim.x + threadIdx.x;
    if (i < NN) g_deg[i] = 0;
    if (blockIdx.x == 0 && threadIdx.x < 32) {
        int lane = threadIdx.x;
        int v = ei[2 * lane + 1];
        unsigned m = __ballot_sync(0xffffffffu, v != 0);
        if (lane == 0) g_stride = (m == 0u) ? 2 : 1;
    }
}

__global__ void k_count_deg(const int* __restrict__ ei) {
    int e = blockIdx.x * blockDim.x + threadIdx.x;
    if (e >= NE) return;
    int st = g_stride;
    int c = ei[(size_t)st * NE + (size_t)e * st];   // target node
    atomicAdd(&g_deg[c], 1);
}

// Per-block exclusive scan of PADDED degrees -> g_rowptr (local part).
// Also computes dis = rsqrt(deg+1) so gemm1 can run right after this.
__global__ void k_scan_local() {
    __shared__ int s[SCAN_BLK];
    int t = threadIdx.x;
    int i = blockIdx.x * SCAN_BLK + t;
    int deg = (i < NN) ? g_deg[i] : 0;
    if (i < NN) g_dis[i] = rsqrtf((float)deg + 1.0f);
    int v = (deg + 7) & ~7;                          // pad to multiple of 8
    s[t] = v;
    __syncthreads();
#pragma unroll
    for (int off = 1; off < SCAN_BLK; off <<= 1) {
        int add = (t >= off) ? s[t - off] : 0;
        __syncthreads();
        s[t] += add;
        __syncthreads();
    }
    if (i < NN) g_rowptr[i] = s[t] - v;   // exclusive (local)
    if (t == SCAN_BLK - 1) g_blocksums[blockIdx.x] = s[t];
}

// ---------------------------------------------------------------------------
// h1 = x @ W1; output ĥ = fp16(dis * h1) to g_ha.
// 256 threads, 128 rows/block; 4 rows × 8 cols per thread.
// Software-pipelined: next k-chunk is prefetched to registers during compute,
// so no GMEM latency ever sits between the two barriers.
__global__ void k_gemm1(const float* __restrict__ x, const float* __restrict__ W) {
    __shared__ alignas(16) float sW[IN_CH * HID];    // 32 KB, [k][c]
    __shared__ alignas(16) float sXt[32 * 128];      // 16 KB, [k_local][row]
    int tid = threadIdx.x;
    int base0 = blockIdx.x * 128;

    for (int i = tid; i < IN_CH * HID; i += 256) sW[i] = W[i];

    int lane = tid & 31;
    int c0 = (tid >> 5) * 8;          // warp → 8 columns
    int lrow = tid & 127;             // loader: row within tile
    int kg = tid >> 7;                // loader: which 16-k group
    int grow = base0 + lrow;
    if (grow >= NN) grow = NN - 1;    // safe pad (stores guarded)
    const float4* xrow = reinterpret_cast<const float4*>(x + (size_t)grow * IN_CH);
    int k0 = kg * 16;

    unsigned long long acc[16];       // [row j][col-pair p] = acc[j*4+p]
#pragma unroll
    for (int i = 0; i < 16; i++) acc[i] = 0ull;

    float4 buf[4];                    // prefetch registers (current chunk)
#pragma unroll
    for (int q = 0; q < 4; q++) buf[q] = xrow[k0 / 4 + q];

    for (int kc = 0; kc < IN_CH; kc += 32) {
        __syncthreads();              // sXt free (previous compute done)
#pragma unroll
        for (int q = 0; q < 4; q++) {
            sXt[(k0 + 4 * q + 0) * 128 + lrow] = buf[q].x;
            sXt[(k0 + 4 * q + 1) * 128 + lrow] = buf[q].y;
            sXt[(k0 + 4 * q + 2) * 128 + lrow] = buf[q].z;
            sXt[(k0 + 4 * q + 3) * 128 + lrow] = buf[q].w;
        }
        if (kc + 32 < IN_CH) {        // prefetch NEXT chunk before the barrier
#pragma unroll
            for (int q = 0; q < 4; q++) buf[q] = xrow[(kc + 32 + k0) / 4 + q];
        }
        __syncthreads();              // sXt ready

#pragma unroll
        for (int k = 0; k < 32; k++) {
            float4 rv = *reinterpret_cast<const float4*>(&sXt[k * 128 + 4 * lane]);
            unsigned long long xp0 = pack2(rv.x);
            unsigned long long xp1 = pack2(rv.y);
            unsigned long long xp2 = pack2(rv.z);
            unsigned long long xp3 = pack2(rv.w);
            ulonglong2 w0 = *reinterpret_cast<const ulonglong2*>(&sW[(kc + k) * HID + c0]);
            ulonglong2 w1 = *reinterpret_cast<const ulonglong2*>(&sW[(kc + k) * HID + c0 + 4]);
            ffma2(acc[0],  xp0, w0.x); ffma2(acc[1],  xp0, w0.y);
            ffma2(acc[2],  xp0, w1.x); ffma2(acc[3],  xp0, w1.y);
            ffma2(acc[4],  xp1, w0.x); ffma2(acc[5],  xp1, w0.y);
            ffma2(acc[6],  xp1, w1.x); ffma2(acc[7],  xp1, w1.y);
            ffma2(acc[8],  xp2, w0.x); ffma2(acc[9],  xp2, w0.y);
            ffma2(acc[10], xp2, w1.x); ffma2(acc[11], xp2, w1.y);
            ffma2(acc[12], xp3, w0.x); ffma2(acc[13], xp3, w0.y);
            ffma2(acc[14], xp3, w1.x); ffma2(acc[15], xp3, w1.y);
        }
    }

#pragma unroll
    for (int j = 0; j < 4; j++) {
        int node = base0 + 4 * lane + j;
        if (node < NN) {
            float d = g_dis[node];
            float o[8];
#pragma unroll
            for (int p = 0; p < 4; p++) unpack2(acc[j * 4 + p], o[2 * p], o[2 * p + 1]);
            H8 v;
#pragma unroll
            for (int p = 0; p < 4; p++)
                v.h[p] = __floats2half2_rn(d * o[2 * p], d * o[2 * p + 1]);
            *reinterpret_cast<H8*>(&g_ha[(size_t)node * 32 + (c0 >> 1)]) = v;
        }
    }
}

// Finalize: every block redundantly scans the 196 block sums in smem, then
// rowptr += prefix; cursor = rowptr; pad slots get ghost source NN.
__global__ void k_finalize_csr() {
    __shared__ int s[256];
    int t = threadIdx.x;
    int bv = (t < SCAN_NB) ? g_blocksums[t] : 0;
    s[t] = bv;
    __syncthreads();
#pragma unroll
    for (int off = 1; off < 256; off <<= 1) {
        int add = (t >= off) ? s[t - off] : 0;
        __syncthreads();
        s[t] += add;
        __syncthreads();
    }
    int i = blockIdx.x * blockDim.x + t;
    if (i < NN) {
        int sb = i >> 9;
        int prefix = (sb > 0) ? s[sb - 1] : 0;
        int rp = g_rowptr[i] + prefix;
        g_rowptr[i] = rp;
        g_cursor[i] = rp;
        int deg = g_deg[i];
        int pdeg = (deg + 7) & ~7;
        for (int j = rp + deg; j < rp + pdeg; j++)
            g_srcbuf[j] = NN;                        // ghost node: features 0
    }
    if (i == 0) g_rowptr[NN] = s[SCAN_NB - 1];
}

// Scatter edge sources into destination-sorted padded order (4B records).
__global__ void k_scatter(const int* __restrict__ ei) {
    int e = blockIdx.x * blockDim.x + threadIdx.x;
    if (e >= NE) return;
    int st = g_stride;
    int r = ei[(size_t)e * st];                     // source
    int c = ei[(size_t)st * NE + (size_t)e * st];   // target
    int pos = atomicAdd(&g_cursor[c], 1);
    g_srcbuf[pos] = r;
}

// ---------------------------------------------------------------------------
// CSR aggregation over PADDED segments (exact multiples of 8 edges).
// WARP per node: 32 lanes × half2 = 64 channels; fp32 accumulation.
// in is pre-scaled ĥ = dis*h, so: out = dis[dst] * (Σ ĥ[src] + ĥ[dst]).
template <int MODE>
__device__ __forceinline__ void agg_body(const __half2* __restrict__ hin,
                                         __half2* __restrict__ hout_h,
                                         float2* __restrict__ hout_f,
                                         const float2* __restrict__ bias2) {
    int node = blockIdx.x * 8 + (threadIdx.x >> 5);   // 12500*8 == NN exactly
    int lane = threadIdx.x & 31;

    int e = g_rowptr[node];
    int end = g_rowptr[node + 1];

    float2 self = __half22float2(hin[(size_t)node * 32 + lane]);
    float acx = self.x, acy = self.y;
    float bcx = 0.0f, bcy = 0.0f;

    const int* __restrict__ sp = g_srcbuf;

    for (; e < end; e += 8) {
        int4 a = *reinterpret_cast<const int4*>(sp + e);
        int4 b = *reinterpret_cast<const int4*>(sp + e + 4);
        float2 v0 = __half22float2(hin[(size_t)a.x * 32 + lane]);
        float2 v1 = __half22float2(hin[(size_t)a.y * 32 + lane]);
        float2 v2 = __half22float2(hin[(size_t)a.z * 32 + lane]);
        float2 v3 = __half22float2(hin[(size_t)a.w * 32 + lane]);
        float2 v4 = __half22float2(hin[(size_t)b.x * 32 + lane]);
        float2 v5 = __half22float2(hin[(size_t)b.y * 32 + lane]);
        float2 v6 = __half22float2(hin[(size_t)b.z * 32 + lane]);
        float2 v7 = __half22float2(hin[(size_t)b.w * 32 + lane]);
        acx += v0.x; acy += v0.y;
        bcx += v1.x; bcy += v1.y;
        acx += v2.x; acy += v2.y;
        bcx += v3.x; bcy += v3.y;
        acx += v4.x; acy += v4.y;
        bcx += v5.x; bcy += v5.y;
        acx += v6.x; acy += v6.y;
        bcx += v7.x; bcy += v7.y;
    }
    float d = g_dis[node];
    acx = d * (acx + bcx);
    acy = d * (acy + bcy);

    if (MODE == 1) {
        float2 b = bias2[lane];
        float hx = fmaxf(acx + b.x, 0.0f);
        float hy = fmaxf(acy + b.y, 0.0f);
        hout_h[(size_t)node * 32 + lane] = __floats2half2_rn(d * hx, d * hy);
    } else {
        hout_f[(size_t)node * 32 + lane] = make_float2(acx, acy);
    }
}

__global__ void k_agg1(const float* __restrict__ bias) {
    agg_body<1>(g_ha, g_hb, nullptr, reinterpret_cast<const float2*>(bias));
}

__global__ void k_agg2() {
    agg_body<0>(g_hb, nullptr, reinterpret_cast<float2*>(g_f), nullptr);
}

// ---------------------------------------------------------------------------
// mu/lv = agg2 @ [Wmu|Wlv] + [bmu|blv]. Register-blocked + pipelined:
// 4 rows × 8 cols per thread, 128 rows/block, 2 k-chunks of 32.
__global__ void k_gemm2(const float* __restrict__ Wmu, const float* __restrict__ bmu,
                        const float* __restrict__ Wlv, const float* __restrict__ blv,
                        float* __restrict__ out) {
    __shared__ alignas(16) float sW[HID * 64];       // 16 KB: [k][c]
    __shared__ alignas(16) float sAt[32 * 128];      // 16 KB, [k_local][row]
    __shared__ alignas(16) float sB[64];
    int tid = threadIdx.x;
    int base0 = blockIdx.x * 128;

    for (int i = tid; i < HID * 64; i += 256) {
        int k = i >> 6, c = i & 63;
        sW[i] = (c < 32) ? Wmu[k * LAT + c] : Wlv[k * LAT + (c - 32)];
    }
    if (tid < 64) sB[tid] = (tid < 32) ? bmu[tid] : blv[tid - 32];

    int lane = tid & 31;
    int c0 = (tid >> 5) * 8;
    int lrow = tid & 127;
    int kg = tid >> 7;
    int grow = base0 + lrow;
    if (grow >= NN) grow = NN - 1;
    const float4* arow = reinterpret_cast<const float4*>(g_f + (size_t)grow * HID);
    int k0 = kg * 16;

    unsigned long long acc[16];
#pragma unroll
    for (int i = 0; i < 16; i++) acc[i] = 0ull;

    float4 buf[4];
#pragma unroll
    for (int q = 0; q < 4; q++) buf[q] = arow[k0 / 4 + q];

    for (int kc = 0; kc < HID; kc += 32) {
        __syncthreads();
#pragma unroll
        for (int q = 0; q < 4; q++) {
            sAt[(k0 + 4 * q + 0) * 128 + lrow] = buf[q].x;
            sAt[(k0 + 4 * q + 1) * 128 + lrow] = buf[q].y;
            sAt[(k0 + 4 * q + 2) * 128 + lrow] = buf[q].z;
            sAt[(k0 + 4 * q + 3) * 128 + lrow] = buf[q].w;
        }
        if (kc + 32 < HID) {
#pragma unroll
            for (int q = 0; q < 4; q++) buf[q] = arow[(kc + 32 + k0) / 4 + q];
        }
        __syncthreads();

#pragma unroll
        for (int k = 0; k < 32; k++) {
            float4 rv = *reinterpret_cast<const float4*>(&sAt[k * 128 + 4 * lane]);
            unsigned long long xp0 = pack2(rv.x);
            unsigned long long xp1 = pack2(rv.y);
            unsigned long long xp2 = pack2(rv.z);
            unsigned long long xp3 = pack2(rv.w);
            ulonglong2 w0 = *reinterpret_cast<const ulonglong2*>(&sW[(kc + k) * 64 + c0]);
            ulonglong2 w1 = *reinterpret_cast<const ulonglong2*>(&sW[(kc + k) * 64 + c0 + 4]);
            ffma2(acc[0],  xp0, w0.x); ffma2(acc[1],  xp0, w0.y);
            ffma2(acc[2],  xp0, w1.x); ffma2(acc[3],  xp0, w1.y);
            ffma2(acc[4],  xp1, w0.x); ffma2(acc[5],  xp1, w0.y);
            ffma2(acc[6],  xp1, w1.x); ffma2(acc[7],  xp1, w1.y);
            ffma2(acc[8],  xp2, w0.x); ffma2(acc[9],  xp2, w0.y);
            ffma2(acc[10], xp2, w1.x); ffma2(acc[11], xp2, w1.y);
            ffma2(acc[12], xp3, w0.x); ffma2(acc[13], xp3, w0.y);
            ffma2(acc[14], xp3, w1.x); ffma2(acc[15], xp3, w1.y);
        }
    }

#pragma unroll
    for (int j = 0; j < 4; j++) {
        int node = base0 + 4 * lane + j;
        if (node < NN) {
            float o[8];
#pragma unroll
            for (int p = 0; p < 4; p++) unpack2(acc[j * 4 + p], o[2 * p], o[2 * p + 1]);
#pragma unroll
            for (int p = 0; p < 8; p++) {
                int c = c0 + p;
                float v = o[p] + sB[c];
                if (c < 32)
                    out[(size_t)node * LAT + c] = v;                            // mu
                else
                    out[(size_t)NN * LAT + (size_t)node * LAT + (c - 32)] = v;  // lv
            }
        }
    }
}

// ---------------------------------------------------------------------------
extern "C" void kernel_launch(void* const* d_in, const int* in_sizes, int n_in,
                              void* d_out, int out_size) {
    const float* x    = (const float*)d_in[0];
    const int*   ei   = (const int*)d_in[1];    // int32 or int64 (detected)
    const float* W1   = (const float*)d_in[2];
    const float* b1   = (const float*)d_in[3];
    const float* Wmu  = (const float*)d_in[4];
    const float* bmu  = (const float*)d_in[5];
    const float* Wlv  = (const float*)d_in[6];
    const float* blv  = (const float*)d_in[7];
    float*       out  = (float*)d_out;

    k_zero_detect<<<(NN + 255) / 256, 256>>>(ei);       // 1
    k_count_deg<<<(NE + 255) / 256, 256>>>(ei);         // 2
    k_scan_local<<<SCAN_NB, SCAN_BLK>>>();              // 3 (also dis)
    k_gemm1<<<(NN + 127) / 128, 256>>>(x, W1);          // 4 ← ncu profiles this
    k_finalize_csr<<<(NN + 255) / 256, 256>>>();        // 5
    k_scatter<<<(NE + 255) / 256, 256>>>(ei);           // 6
    k_agg1<<<NN / 8, 256>>>(b1);                        // 7
    k_agg2<<<NN / 8, 256>>>();                          // 8
    k_gemm2<<<(NN + 127) / 128, 256>>>(Wmu, bmu, Wlv, blv, out);  // 9
}

// round 13
// speedup vs baseline: 1.5258x; 1.2268x over previous
#include <cuda_runtime.h>
#include <cuda_fp16.h>

#define NN 100000
#define NE 1600000
#define IN_CH 128
#define HID 64
#define LAT 32

#define SCAN_BLK 512
#define SCAN_NB ((NN + SCAN_BLK - 1) / SCAN_BLK)   // 196
#define NEP (NE + 8 * NN)                          // padded edge capacity

// Scratch (static __device__ — no allocations allowed)
__device__ int     g_stride;              // 1 = edge_index int32, 2 = int64
__device__ int     g_deg[NN];
__device__ int     g_rowptr[NN + 1];      // padded CSR offsets (multiples of 8)
__device__ int     g_cursor[NN];
__device__ int     g_blocksums[SCAN_NB];
__device__ int     g_srcbuf[NEP];         // per-edge source index (pad = NN)
__device__ float   g_dis[NN];
__device__ __half2 g_ha[(NN + 1) * 32];   // dis*h1 fp16; ghost node NN stays 0
__device__ __half2 g_hb[(NN + 1) * 32];   // dis*relu(...) fp16; ghost stays 0
__device__ float   g_f[NN * HID];         // agg2 output fp32 (gemm2 input)

struct alignas(16) H8 { __half2 h[4]; };

// ---------------------------------------------------------------------------
__device__ __forceinline__ void ffma2(unsigned long long& acc,
                                      unsigned long long a,
                                      unsigned long long b) {
    asm("fma.rn.f32x2 %0, %1, %2, %0;" : "+l"(acc) : "l"(a), "l"(b));
}
__device__ __forceinline__ unsigned long long pack2(float v) {
    unsigned long long r;
    asm("mov.b64 %0, {%1, %1};" : "=l"(r) : "f"(v));
    return r;
}
__device__ __forceinline__ void unpack2(unsigned long long p, float& lo, float& hi) {
    asm("mov.b64 {%0, %1}, %2;" : "=f"(lo), "=f"(hi) : "l"(p));
}
__device__ __forceinline__ unsigned smem_u32(const void* p) {
    return (unsigned)__cvta_generic_to_shared(p);
}

// ---------------------------------------------------------------------------
// Zero degrees; block 0 warp 0 detects edge_index dtype (int64 → odd words 0).
__global__ void k_zero_detect(const int* __restrict__ ei) {
    int i = blockIdx.x * blockDim.x + threadIdx.x;
    if (i < NN) g_deg[i] = 0;
    if (blockIdx.x == 0 && threadIdx.x < 32) {
        int lane = threadIdx.x;
        int v = ei[2 * lane + 1];
        unsigned m = __ballot_sync(0xffffffffu, v != 0);
        if (lane == 0) g_stride = (m == 0u) ? 2 : 1;
    }
}

__global__ void k_count_deg(const int* __restrict__ ei) {
    int e = blockIdx.x * blockDim.x + threadIdx.x;
    if (e >= NE) return;
    int st = g_stride;
    int c = ei[(size_t)st * NE + (size_t)e * st];   // target node
    atomicAdd(&g_deg[c], 1);
}

// Per-block exclusive scan of PADDED degrees -> g_rowptr (local part).
// Also computes dis = rsqrt(deg+1) so gemm1 can run right after this.
__global__ void k_scan_local() {
    __shared__ int s[SCAN_BLK];
    int t = threadIdx.x;
    int i = blockIdx.x * SCAN_BLK + t;
    int deg = (i < NN) ? g_deg[i] : 0;
    if (i < NN) g_dis[i] = rsqrtf((float)deg + 1.0f);
    int v = (deg + 7) & ~7;                          // pad to multiple of 8
    s[t] = v;
    __syncthreads();
#pragma unroll
    for (int off = 1; off < SCAN_BLK; off <<= 1) {
        int add = (t >= off) ? s[t - off] : 0;
        __syncthreads();
        s[t] += add;
        __syncthreads();
    }
    if (i < NN) g_rowptr[i] = s[t] - v;   // exclusive (local)
    if (t == SCAN_BLK - 1) g_blocksums[blockIdx.x] = s[t];
}

// ---------------------------------------------------------------------------
// h1 = x @ W1 via HMMA (mma.sync m16n8k16, fp16 in, fp32 acc).
// 256 threads, 128 rows/block, 64 cols. x/W converted to fp16 while staging
// into XOR-swizzled smem (conflict-free ldmatrix). One sync, then sync-free
// mainloop. Epilogue: ĥ = fp16(dis * h1) → g_ha.
__global__ void k_gemm1(const float* __restrict__ x, const float* __restrict__ W) {
    __shared__ alignas(16) __half sA[128 * 128];   // 32 KB: [row][k] swizzled
    __shared__ alignas(16) __half sW[128 * 64];    // 16 KB: [k][n]  swizzled
    int tid = threadIdx.x;
    int base0 = blockIdx.x * 128;

    // Stage x tile: 2048 16B-chunks; chunk (row, c) at row*256B + (c^(row&7))*16B.
    for (int idx = tid; idx < 128 * 16; idx += 256) {
        int row = idx >> 4, c = idx & 15;
        int grow = base0 + row;
        if (grow >= NN) grow = NN - 1;             // junk ok, stores guarded
        const float4* src = reinterpret_cast<const float4*>(
            x + (size_t)grow * IN_CH + c * 8);
        float4 f0 = src[0], f1 = src[1];
        H8 h;
        h.h[0] = __floats2half2_rn(f0.x, f0.y);
        h.h[1] = __floats2half2_rn(f0.z, f0.w);
        h.h[2] = __floats2half2_rn(f1.x, f1.y);
        h.h[3] = __floats2half2_rn(f1.z, f1.w);
        *reinterpret_cast<H8*>(&sA[row * 128 + ((c ^ (row & 7)) * 8)]) = h;
    }
    // Stage W tile: 1024 chunks; chunk (k, c) at k*128B + (c^(k&7))*16B.
    for (int idx = tid; idx < 128 * 8; idx += 256) {
        int k = idx >> 3, c = idx & 7;
        const float4* src = reinterpret_cast<const float4*>(W + k * HID + c * 8);
        float4 f0 = src[0], f1 = src[1];
        H8 h;
        h.h[0] = __floats2half2_rn(f0.x, f0.y);
        h.h[1] = __floats2half2_rn(f0.z, f0.w);
        h.h[2] = __floats2half2_rn(f1.x, f1.y);
        h.h[3] = __floats2half2_rn(f1.z, f1.w);
        *reinterpret_cast<H8*>(&sW[k * 64 + ((c ^ (k & 7)) * 8)]) = h;
    }
    __syncthreads();

    int warp = tid >> 5;
    int lane = tid & 31;
    int wrow = warp * 16;                          // warp's 16 rows

    float acc[8][4];                               // 8 n-tiles × 4 C regs
#pragma unroll
    for (int n = 0; n < 8; n++)
#pragma unroll
        for (int j = 0; j < 4; j++) acc[n][j] = 0.0f;

    // Precompute ldmatrix lane addresses.
    // A (.x4): t=lane>>3, r=lane&7: row = wrow + (t&1)*8 + r, chunk = 2*kc + (t>>1)
    int a_t = lane >> 3, a_r = lane & 7;
    int a_row = wrow + (a_t & 1) * 8 + a_r;
    int a_chsel = a_t >> 1;                        // 0 or 1 (which 8-k half)
    // B (.x4.trans): k_row = 16*kc + (t&1)*8 + r, chunk = nt + (t>>1)
    int b_kr = (a_t & 1) * 8 + a_r;
    int b_csel = a_t >> 1;

#pragma unroll
    for (int kc = 0; kc < 8; kc++) {
        // A fragment: 16 rows × 16 k
        unsigned a0, a1, a2, a3;
        {
            int chunk = 2 * kc + a_chsel;
            unsigned addr = smem_u32(&sA[a_row * 128 + ((chunk ^ (a_row & 7)) * 8)]);
            asm volatile("ldmatrix.sync.aligned.m8n8.x4.shared.b16 {%0,%1,%2,%3}, [%4];"
                         : "=r"(a0), "=r"(a1), "=r"(a2), "=r"(a3) : "r"(addr));
        }
        int krow = 16 * kc + b_kr;
#pragma unroll
        for (int np = 0; np < 4; np++) {           // pairs of n-tiles
            unsigned b0, b1, b2, b3;
            int chunk = 2 * np + b_csel;
            unsigned addr = smem_u32(&sW[krow * 64 + ((chunk ^ (krow & 7)) * 8)]);
            asm volatile("ldmatrix.sync.aligned.m8n8.x4.trans.shared.b16 {%0,%1,%2,%3}, [%4];"
                         : "=r"(b0), "=r"(b1), "=r"(b2), "=r"(b3) : "r"(addr));
            asm volatile("mma.sync.aligned.m16n8k16.row.col.f32.f16.f16.f32 "
                         "{%0,%1,%2,%3}, {%4,%5,%6,%7}, {%8,%9}, {%0,%1,%2,%3};"
                         : "+f"(acc[2 * np][0]), "+f"(acc[2 * np][1]),
                           "+f"(acc[2 * np][2]), "+f"(acc[2 * np][3])
                         : "r"(a0), "r"(a1), "r"(a2), "r"(a3), "r"(b0), "r"(b1));
            asm volatile("mma.sync.aligned.m16n8k16.row.col.f32.f16.f16.f32 "
                         "{%0,%1,%2,%3}, {%4,%5,%6,%7}, {%8,%9}, {%0,%1,%2,%3};"
                         : "+f"(acc[2 * np + 1][0]), "+f"(acc[2 * np + 1][1]),
                           "+f"(acc[2 * np + 1][2]), "+f"(acc[2 * np + 1][3])
                         : "r"(a0), "r"(a1), "r"(a2), "r"(a3), "r"(b2), "r"(b3));
        }
    }

    // Epilogue: C lane map: rows wrow + lane/4 (+8), cols nt*8 + (lane%3... %4)*2.
    int r0 = wrow + (lane >> 2);
    int cq = lane & 3;                             // half2 index within n-tile
#pragma unroll
    for (int half = 0; half < 2; half++) {
        int node = base0 + r0 + half * 8;
        if (node < NN) {
            float d = g_dis[node];
#pragma unroll
            for (int nt = 0; nt < 8; nt++) {
                float v0 = acc[nt][2 * half + 0] * d;
                float v1 = acc[nt][2 * half + 1] * d;
                g_ha[(size_t)node * 32 + nt * 4 + cq] = __floats2half2_rn(v0, v1);
            }
        }
    }
}

// Finalize: every block redundantly scans the 196 block sums in smem, then
// rowptr += prefix; cursor = rowptr; pad slots get ghost source NN.
__global__ void k_finalize_csr() {
    __shared__ int s[256];
    int t = threadIdx.x;
    int bv = (t < SCAN_NB) ? g_blocksums[t] : 0;
    s[t] = bv;
    __syncthreads();
#pragma unroll
    for (int off = 1; off < 256; off <<= 1) {
        int add = (t >= off) ? s[t - off] : 0;
        __syncthreads();
        s[t] += add;
        __syncthreads();
    }
    int i = blockIdx.x * blockDim.x + t;
    if (i < NN) {
        int sb = i >> 9;
        int prefix = (sb > 0) ? s[sb - 1] : 0;
        int rp = g_rowptr[i] + prefix;
        g_rowptr[i] = rp;
        g_cursor[i] = rp;
        int deg = g_deg[i];
        int pdeg = (deg + 7) & ~7;
        for (int j = rp + deg; j < rp + pdeg; j++)
            g_srcbuf[j] = NN;                        // ghost node: features 0
    }
    if (i == 0) g_rowptr[NN] = s[SCAN_NB - 1];
}

// Scatter edge sources into destination-sorted padded order (4B records).
__global__ void k_scatter(const int* __restrict__ ei) {
    int e = blockIdx.x * blockDim.x + threadIdx.x;
    if (e >= NE) return;
    int st = g_stride;
    int r = ei[(size_t)e * st];                     // source
    int c = ei[(size_t)st * NE + (size_t)e * st];   // target
    int pos = atomicAdd(&g_cursor[c], 1);
    g_srcbuf[pos] = r;
}

// ---------------------------------------------------------------------------
// CSR aggregation over PADDED segments (exact multiples of 8 edges).
// WARP per node: 32 lanes × half2 = 64 channels; fp32 accumulation.
// in is pre-scaled ĥ = dis*h, so: out = dis[dst] * (Σ ĥ[src] + ĥ[dst]).
template <int MODE>
__device__ __forceinline__ void agg_body(const __half2* __restrict__ hin,
                                         __half2* __restrict__ hout_h,
                                         float2* __restrict__ hout_f,
                                         const float2* __restrict__ bias2) {
    int node = blockIdx.x * 8 + (threadIdx.x >> 5);   // 12500*8 == NN exactly
    int lane = threadIdx.x & 31;

    int e = g_rowptr[node];
    int end = g_rowptr[node + 1];

    float2 self = __half22float2(hin[(size_t)node * 32 + lane]);
    float acx = self.x, acy = self.y;
    float bcx = 0.0f, bcy = 0.0f;

    const int* __restrict__ sp = g_srcbuf;

    for (; e < end; e += 8) {
        int4 a = *reinterpret_cast<const int4*>(sp + e);
        int4 b = *reinterpret_cast<const int4*>(sp + e + 4);
        float2 v0 = __half22float2(hin[(size_t)a.x * 32 + lane]);
        float2 v1 = __half22float2(hin[(size_t)a.y * 32 + lane]);
        float2 v2 = __half22float2(hin[(size_t)a.z * 32 + lane]);
        float2 v3 = __half22float2(hin[(size_t)a.w * 32 + lane]);
        float2 v4 = __half22float2(hin[(size_t)b.x * 32 + lane]);
        float2 v5 = __half22float2(hin[(size_t)b.y * 32 + lane]);
        float2 v6 = __half22float2(hin[(size_t)b.z * 32 + lane]);
        float2 v7 = __half22float2(hin[(size_t)b.w * 32 + lane]);
        acx += v0.x; acy += v0.y;
        bcx += v1.x; bcy += v1.y;
        acx += v2.x; acy += v2.y;
        bcx += v3.x; bcy += v3.y;
        acx += v4.x; acy += v4.y;
        bcx += v5.x; bcy += v5.y;
        acx += v6.x; acy += v6.y;
        bcx += v7.x; bcy += v7.y;
    }
    float d = g_dis[node];
    acx = d * (acx + bcx);
    acy = d * (acy + bcy);

    if (MODE == 1) {
        float2 b = bias2[lane];
        float hx = fmaxf(acx + b.x, 0.0f);
        float hy = fmaxf(acy + b.y, 0.0f);
        hout_h[(size_t)node * 32 + lane] = __floats2half2_rn(d * hx, d * hy);
    } else {
        hout_f[(size_t)node * 32 + lane] = make_float2(acx, acy);
    }
}

__global__ void k_agg1(const float* __restrict__ bias) {
    agg_body<1>(g_ha, g_hb, nullptr, reinterpret_cast<const float2*>(bias));
}

__global__ void k_agg2() {
    agg_body<0>(g_hb, nullptr, reinterpret_cast<float2*>(g_f), nullptr);
}

// ---------------------------------------------------------------------------
// mu/lv = agg2 @ [Wmu|Wlv] + [bmu|blv]. Register-blocked + pipelined FFMA2:
// 4 rows × 8 cols per thread, 128 rows/block, 2 k-chunks of 32.
__global__ void k_gemm2(const float* __restrict__ Wmu, const float* __restrict__ bmu,
                        const float* __restrict__ Wlv, const float* __restrict__ blv,
                        float* __restrict__ out) {
    __shared__ alignas(16) float sW[HID * 64];       // 16 KB: [k][c]
    __shared__ alignas(16) float sAt[32 * 128];      // 16 KB, [k_local][row]
    __shared__ alignas(16) float sB[64];
    int tid = threadIdx.x;
    int base0 = blockIdx.x * 128;

    for (int i = tid; i < HID * 64; i += 256) {
        int k = i >> 6, c = i & 63;
        sW[i] = (c < 32) ? Wmu[k * LAT + c] : Wlv[k * LAT + (c - 32)];
    }
    if (tid < 64) sB[tid] = (tid < 32) ? bmu[tid] : blv[tid - 32];

    int lane = tid & 31;
    int c0 = (tid >> 5) * 8;
    int lrow = tid & 127;
    int kg = tid >> 7;
    int grow = base0 + lrow;
    if (grow >= NN) grow = NN - 1;
    const float4* arow = reinterpret_cast<const float4*>(g_f + (size_t)grow * HID);
    int k0 = kg * 16;

    unsigned long long acc[16];
#pragma unroll
    for (int i = 0; i < 16; i++) acc[i] = 0ull;

    float4 buf[4];
#pragma unroll
    for (int q = 0; q < 4; q++) buf[q] = arow[k0 / 4 + q];

    for (int kc = 0; kc < HID; kc += 32) {
        __syncthreads();
#pragma unroll
        for (int q = 0; q < 4; q++) {
            sAt[(k0 + 4 * q + 0) * 128 + lrow] = buf[q].x;
            sAt[(k0 + 4 * q + 1) * 128 + lrow] = buf[q].y;
            sAt[(k0 + 4 * q + 2) * 128 + lrow] = buf[q].z;
            sAt[(k0 + 4 * q + 3) * 128 + lrow] = buf[q].w;
        }
        if (kc + 32 < HID) {
#pragma unroll
            for (int q = 0; q < 4; q++) buf[q] = arow[(kc + 32 + k0) / 4 + q];
        }
        __syncthreads();

#pragma unroll
        for (int k = 0; k < 32; k++) {
            float4 rv = *reinterpret_cast<const float4*>(&sAt[k * 128 + 4 * lane]);
            unsigned long long xp0 = pack2(rv.x);
            unsigned long long xp1 = pack2(rv.y);
            unsigned long long xp2 = pack2(rv.z);
            unsigned long long xp3 = pack2(rv.w);
            ulonglong2 w0 = *reinterpret_cast<const ulonglong2*>(&sW[(kc + k) * 64 + c0]);
            ulonglong2 w1 = *reinterpret_cast<const ulonglong2*>(&sW[(kc + k) * 64 + c0 + 4]);
            ffma2(acc[0],  xp0, w0.x); ffma2(acc[1],  xp0, w0.y);
            ffma2(acc[2],  xp0, w1.x); ffma2(acc[3],  xp0, w1.y);
            ffma2(acc[4],  xp1, w0.x); ffma2(acc[5],  xp1, w0.y);
            ffma2(acc[6],  xp1, w1.x); ffma2(acc[7],  xp1, w1.y);
            ffma2(acc[8],  xp2, w0.x); ffma2(acc[9],  xp2, w0.y);
            ffma2(acc[10], xp2, w1.x); ffma2(acc[11], xp2, w1.y);
            ffma2(acc[12], xp3, w0.x); ffma2(acc[13], xp3, w0.y);
            ffma2(acc[14], xp3, w1.x); ffma2(acc[15], xp3, w1.y);
        }
    }

#pragma unroll
    for (int j = 0; j < 4; j++) {
        int node = base0 + 4 * lane + j;
        if (node < NN) {
            float o[8];
#pragma unroll
            for (int p = 0; p < 4; p++) unpack2(acc[j * 4 + p], o[2 * p], o[2 * p + 1]);
#pragma unroll
            for (int p = 0; p < 8; p++) {
                int c = c0 + p;
                float v = o[p] + sB[c];
                if (c < 32)
                    out[(size_t)node * LAT + c] = v;                            // mu
                else
                    out[(size_t)NN * LAT + (size_t)node * LAT + (c - 32)] = v;  // lv
            }
        }
    }
}

// ---------------------------------------------------------------------------
extern "C" void kernel_launch(void* const* d_in, const int* in_sizes, int n_in,
                              void* d_out, int out_size) {
    const float* x    = (const float*)d_in[0];
    const int*   ei   = (const int*)d_in[1];    // int32 or int64 (detected)
    const float* W1   = (const float*)d_in[2];
    const float* b1   = (const float*)d_in[3];
    const float* Wmu  = (const float*)d_in[4];
    const float* bmu  = (const float*)d_in[5];
    const float* Wlv  = (const float*)d_in[6];
    const float* blv  = (const float*)d_in[7];
    float*       out  = (float*)d_out;

    k_zero_detect<<<(NN + 255) / 256, 256>>>(ei);       // 1
    k_count_deg<<<(NE + 255) / 256, 256>>>(ei);         // 2
    k_scan_local<<<SCAN_NB, SCAN_BLK>>>();              // 3 (also dis)
    k_gemm1<<<(NN + 127) / 128, 256>>>(x, W1);          // 4 ← ncu profiles this
    k_finalize_csr<<<(NN + 255) / 256, 256>>>();        // 5
    k_scatter<<<(NE + 255) / 256, 256>>>(ei);           // 6
    k_agg1<<<NN / 8, 256>>>(b1);                        // 7
    k_agg2<<<NN / 8, 256>>>();                          // 8
    k_gemm2<<<(NN + 127) / 128, 256>>>(Wmu, bmu, Wlv, blv, out);  // 9
}

// round 14
// speedup vs baseline: 1.9996x; 1.3105x over previous
#include <cuda_runtime.h>
#include <cuda_fp16.h>

#define NN 100000
#define NE 1600000
#define IN_CH 128
#define HID 64
#define LAT 32

#define SCAN_BLK 512
#define SCAN_NB ((NN + SCAN_BLK - 1) / SCAN_BLK)   // 196
#define NEP (NE + 8 * NN)                          // padded edge capacity

// Scratch (static __device__ — no allocations allowed)
__device__ int     g_stride;              // 1 = edge_index int32, 2 = int64
__device__ int     g_deg[NN];
__device__ int     g_rowptr[NN + 1];      // padded CSR offsets (multiples of 8)
__device__ int     g_cursor[NN];
__device__ int     g_blocksums[SCAN_NB];
__device__ int     g_srcbuf[NEP];         // per-edge source index (pad = NN)
__device__ float   g_dis[NN];
__device__ __half2 g_ha[(NN + 1) * 32];   // dis*h1 fp16; later agg2 out (fp16)
__device__ __half2 g_hb[(NN + 1) * 32];   // dis*relu(...) fp16; ghost stays 0

struct alignas(16) H8 { __half2 h[4]; };

// ---------------------------------------------------------------------------
__device__ __forceinline__ unsigned smem_u32(const void* p) {
    return (unsigned)__cvta_generic_to_shared(p);
}
__device__ __forceinline__ H8 cvt8(float4 f0, float4 f1) {
    H8 h;
    h.h[0] = __floats2half2_rn(f0.x, f0.y);
    h.h[1] = __floats2half2_rn(f0.z, f0.w);
    h.h[2] = __floats2half2_rn(f1.x, f1.y);
    h.h[3] = __floats2half2_rn(f1.z, f1.w);
    return h;
}

// ---------------------------------------------------------------------------
// Zero degrees; block 0 warp 0 detects edge_index dtype (int64 → odd words 0).
__global__ void k_zero_detect(const int* __restrict__ ei) {
    int i = blockIdx.x * blockDim.x + threadIdx.x;
    if (i < NN) g_deg[i] = 0;
    if (blockIdx.x == 0 && threadIdx.x < 32) {
        int lane = threadIdx.x;
        int v = ei[2 * lane + 1];
        unsigned m = __ballot_sync(0xffffffffu, v != 0);
        if (lane == 0) g_stride = (m == 0u) ? 2 : 1;
    }
}

__global__ void k_count_deg(const int* __restrict__ ei) {
    int e = blockIdx.x * blockDim.x + threadIdx.x;
    if (e >= NE) return;
    int st = g_stride;
    int c = ei[(size_t)st * NE + (size_t)e * st];   // target node
    atomicAdd(&g_deg[c], 1);
}

// Per-block exclusive scan of PADDED degrees -> g_rowptr (local part).
// Also computes dis = rsqrt(deg+1) so gemm1 can run right after this.
__global__ void k_scan_local() {
    __shared__ int s[SCAN_BLK];
    int t = threadIdx.x;
    int i = blockIdx.x * SCAN_BLK + t;
    int deg = (i < NN) ? g_deg[i] : 0;
    if (i < NN) g_dis[i] = rsqrtf((float)deg + 1.0f);
    int v = (deg + 7) & ~7;                          // pad to multiple of 8
    s[t] = v;
    __syncthreads();
#pragma unroll
    for (int off = 1; off < SCAN_BLK; off <<= 1) {
        int add = (t >= off) ? s[t - off] : 0;
        __syncthreads();
        s[t] += add;
        __syncthreads();
    }
    if (i < NN) g_rowptr[i] = s[t] - v;   // exclusive (local)
    if (t == SCAN_BLK - 1) g_blocksums[blockIdx.x] = s[t];
}

// ---------------------------------------------------------------------------
// h1 = x @ W1 via HMMA (mma.sync m16n8k16, fp16 in, fp32 acc).
// 256 threads, 128 rows/block. Staging uses 8-deep batched LDG.128 for MLP.
// Epilogue: ĥ = fp16(dis * h1) → g_ha.
__global__ void k_gemm1(const float* __restrict__ x, const float* __restrict__ W) {
    __shared__ alignas(16) __half sA[128 * 128];   // 32 KB: [row][k] swizzled
    __shared__ alignas(16) __half sW[128 * 64];    // 16 KB: [k][n]  swizzled
    int tid = threadIdx.x;
    int base0 = blockIdx.x * 128;

    // Stage x tile with deep MLP: 2048 chunks, 2 batches × (8 LDG.128 → cvt/STS).
#pragma unroll
    for (int b = 0; b < 2; b++) {
        float4 f[8];
#pragma unroll
        for (int q = 0; q < 4; q++) {
            int idx = tid + (b * 4 + q) * 256;
            int row = idx >> 4, c = idx & 15;
            int grow = base0 + row;
            if (grow >= NN) grow = NN - 1;         // junk ok, stores guarded
            const float4* src = reinterpret_cast<const float4*>(
                x + (size_t)grow * IN_CH + c * 8);
            f[2 * q] = src[0];
            f[2 * q + 1] = src[1];
        }
#pragma unroll
        for (int q = 0; q < 4; q++) {
            int idx = tid + (b * 4 + q) * 256;
            int row = idx >> 4, c = idx & 15;
            H8 h = cvt8(f[2 * q], f[2 * q + 1]);
            *reinterpret_cast<H8*>(&sA[row * 128 + ((c ^ (row & 7)) * 8)]) = h;
        }
    }
    // Stage W tile: 1024 chunks; chunk (k, c) at k*128B + (c^(k&7))*16B.
    for (int idx = tid; idx < 128 * 8; idx += 256) {
        int k = idx >> 3, c = idx & 7;
        const float4* src = reinterpret_cast<const float4*>(W + k * HID + c * 8);
        H8 h = cvt8(src[0], src[1]);
        *reinterpret_cast<H8*>(&sW[k * 64 + ((c ^ (k & 7)) * 8)]) = h;
    }
    __syncthreads();

    int warp = tid >> 5;
    int lane = tid & 31;
    int wrow = warp * 16;

    float acc[8][4];
#pragma unroll
    for (int n = 0; n < 8; n++)
#pragma unroll
        for (int j = 0; j < 4; j++) acc[n][j] = 0.0f;

    int a_t = lane >> 3, a_r = lane & 7;
    int a_row = wrow + (a_t & 1) * 8 + a_r;
    int a_chsel = a_t >> 1;
    int b_kr = (a_t & 1) * 8 + a_r;
    int b_csel = a_t >> 1;

#pragma unroll
    for (int kc = 0; kc < 8; kc++) {
        unsigned a0, a1, a2, a3;
        {
            int chunk = 2 * kc + a_chsel;
            unsigned addr = smem_u32(&sA[a_row * 128 + ((chunk ^ (a_row & 7)) * 8)]);
            asm volatile("ldmatrix.sync.aligned.m8n8.x4.shared.b16 {%0,%1,%2,%3}, [%4];"
                         : "=r"(a0), "=r"(a1), "=r"(a2), "=r"(a3) : "r"(addr));
        }
        int krow = 16 * kc + b_kr;
#pragma unroll
        for (int np = 0; np < 4; np++) {
            unsigned b0, b1, b2, b3;
            int chunk = 2 * np + b_csel;
            unsigned addr = smem_u32(&sW[krow * 64 + ((chunk ^ (krow & 7)) * 8)]);
            asm volatile("ldmatrix.sync.aligned.m8n8.x4.trans.shared.b16 {%0,%1,%2,%3}, [%4];"
                         : "=r"(b0), "=r"(b1), "=r"(b2), "=r"(b3) : "r"(addr));
            asm volatile("mma.sync.aligned.m16n8k16.row.col.f32.f16.f16.f32 "
                         "{%0,%1,%2,%3}, {%4,%5,%6,%7}, {%8,%9}, {%0,%1,%2,%3};"
                         : "+f"(acc[2 * np][0]), "+f"(acc[2 * np][1]),
                           "+f"(acc[2 * np][2]), "+f"(acc[2 * np][3])
                         : "r"(a0), "r"(a1), "r"(a2), "r"(a3), "r"(b0), "r"(b1));
            asm volatile("mma.sync.aligned.m16n8k16.row.col.f32.f16.f16.f32 "
                         "{%0,%1,%2,%3}, {%4,%5,%6,%7}, {%8,%9}, {%0,%1,%2,%3};"
                         : "+f"(acc[2 * np + 1][0]), "+f"(acc[2 * np + 1][1]),
                           "+f"(acc[2 * np + 1][2]), "+f"(acc[2 * np + 1][3])
                         : "r"(a0), "r"(a1), "r"(a2), "r"(a3), "r"(b2), "r"(b3));
        }
    }

    int r0 = wrow + (lane >> 2);
    int cq = lane & 3;
#pragma unroll
    for (int half = 0; half < 2; half++) {
        int node = base0 + r0 + half * 8;
        if (node < NN) {
            float d = g_dis[node];
#pragma unroll
            for (int nt = 0; nt < 8; nt++) {
                float v0 = acc[nt][2 * half + 0] * d;
                float v1 = acc[nt][2 * half + 1] * d;
                g_ha[(size_t)node * 32 + nt * 4 + cq] = __floats2half2_rn(v0, v1);
            }
        }
    }
}

// Finalize: every block redundantly scans the 196 block sums in smem, then
// rowptr += prefix; cursor = rowptr; pad slots get ghost source NN.
__global__ void k_finalize_csr() {
    __shared__ int s[256];
    int t = threadIdx.x;
    int bv = (t < SCAN_NB) ? g_blocksums[t] : 0;
    s[t] = bv;
    __syncthreads();
#pragma unroll
    for (int off = 1; off < 256; off <<= 1) {
        int add = (t >= off) ? s[t - off] : 0;
        __syncthreads();
        s[t] += add;
        __syncthreads();
    }
    int i = blockIdx.x * blockDim.x + t;
    if (i < NN) {
        int sb = i >> 9;
        int prefix = (sb > 0) ? s[sb - 1] : 0;
        int rp = g_rowptr[i] + prefix;
        g_rowptr[i] = rp;
        g_cursor[i] = rp;
        int deg = g_deg[i];
        int pdeg = (deg + 7) & ~7;
        for (int j = rp + deg; j < rp + pdeg; j++)
            g_srcbuf[j] = NN;                        // ghost node: features 0
    }
    if (i == 0) g_rowptr[NN] = s[SCAN_NB - 1];
}

// Scatter edge sources into destination-sorted padded order (4B records).
__global__ void k_scatter(const int* __restrict__ ei) {
    int e = blockIdx.x * blockDim.x + threadIdx.x;
    if (e >= NE) return;
    int st = g_stride;
    int r = ei[(size_t)e * st];                     // source
    int c = ei[(size_t)st * NE + (size_t)e * st];   // target
    int pos = atomicAdd(&g_cursor[c], 1);
    g_srcbuf[pos] = r;
}

// ---------------------------------------------------------------------------
// CSR aggregation over PADDED segments (exact multiples of 8 edges).
// WARP per node: 32 lanes × half2 = 64 channels; fp32 accumulation.
// in is pre-scaled ĥ = dis*h, so: out = dis[dst] * (Σ ĥ[src] + ĥ[dst]).
// MODE 1: +bias, relu, re-pre-scale by dis, fp16 out (for next gather).
// MODE 0: plain dis-scaled result, fp16 out (feeds HMMA gemm2).
template <int MODE>
__device__ __forceinline__ void agg_body(const __half2* __restrict__ hin,
                                         __half2* __restrict__ hout,
                                         const float2* __restrict__ bias2) {
    int node = blockIdx.x * 8 + (threadIdx.x >> 5);   // 12500*8 == NN exactly
    int lane = threadIdx.x & 31;

    int e = g_rowptr[node];
    int end = g_rowptr[node + 1];

    float2 self = __half22float2(hin[(size_t)node * 32 + lane]);
    float acx = self.x, acy = self.y;
    float bcx = 0.0f, bcy = 0.0f;

    const int* __restrict__ sp = g_srcbuf;

    for (; e < end; e += 8) {
        int4 a = *reinterpret_cast<const int4*>(sp + e);
        int4 b = *reinterpret_cast<const int4*>(sp + e + 4);
        float2 v0 = __half22float2(hin[(size_t)a.x * 32 + lane]);
        float2 v1 = __half22float2(hin[(size_t)a.y * 32 + lane]);
        float2 v2 = __half22float2(hin[(size_t)a.z * 32 + lane]);
        float2 v3 = __half22float2(hin[(size_t)a.w * 32 + lane]);
        float2 v4 = __half22float2(hin[(size_t)b.x * 32 + lane]);
        float2 v5 = __half22float2(hin[(size_t)b.y * 32 + lane]);
        float2 v6 = __half22float2(hin[(size_t)b.z * 32 + lane]);
        float2 v7 = __half22float2(hin[(size_t)b.w * 32 + lane]);
        acx += v0.x; acy += v0.y;
        bcx += v1.x; bcy += v1.y;
        acx += v2.x; acy += v2.y;
        bcx += v3.x; bcy += v3.y;
        acx += v4.x; acy += v4.y;
        bcx += v5.x; bcy += v5.y;
        acx += v6.x; acy += v6.y;
        bcx += v7.x; bcy += v7.y;
    }
    float d = g_dis[node];
    acx = d * (acx + bcx);
    acy = d * (acy + bcy);

    if (MODE == 1) {
        float2 b = bias2[lane];
        float hx = fmaxf(acx + b.x, 0.0f);
        float hy = fmaxf(acy + b.y, 0.0f);
        hout[(size_t)node * 32 + lane] = __floats2half2_rn(d * hx, d * hy);
    } else {
        hout[(size_t)node * 32 + lane] = __floats2half2_rn(acx, acy);
    }
}

__global__ void k_agg1(const float* __restrict__ bias) {
    agg_body<1>(g_ha, g_hb, reinterpret_cast<const float2*>(bias));
}

__global__ void k_agg2() {
    agg_body<0>(g_hb, g_ha, nullptr);    // g_ha reused: agg2 output (fp16)
}

// ---------------------------------------------------------------------------
// mu/lv = agg2 @ [Wmu|Wlv] + [bmu|blv] via HMMA. A = g_ha (fp16, no cvt),
// B = combined 64×64 fp16 W. 256 threads, 128 rows/block, 4 k-chunks.
__global__ void k_gemm2(const float* __restrict__ Wmu, const float* __restrict__ bmu,
                        const float* __restrict__ Wlv, const float* __restrict__ blv,
                        float* __restrict__ out) {
    __shared__ alignas(16) __half sA[128 * 64];    // 16 KB: [row][k] swizzled
    __shared__ alignas(16) __half sW[64 * 64];     // 8 KB:  [k][n]  swizzled
    __shared__ alignas(16) float sB[64];
    int tid = threadIdx.x;
    int base0 = blockIdx.x * 128;

    // Stage W (combined mu|lv): 512 chunks; chunk (k, c): cols c*8..c*8+7.
    for (int idx = tid; idx < 64 * 8; idx += 256) {
        int k = idx >> 3, c = idx & 7;
        const float* src = (c < 4) ? (Wmu + k * LAT + c * 8)
                                   : (Wlv + k * LAT + (c - 4) * 8);
        const float4* s4 = reinterpret_cast<const float4*>(src);
        H8 h = cvt8(s4[0], s4[1]);
        *reinterpret_cast<H8*>(&sW[k * 64 + ((c ^ (k & 7)) * 8)]) = h;
    }
    if (tid < 64) sB[tid] = (tid < 32) ? bmu[tid] : blv[tid - 32];
    // Stage A from g_ha (already fp16): 1024 chunks of 16B.
    for (int idx = tid; idx < 128 * 8; idx += 256) {
        int row = idx >> 3, c = idx & 7;
        int grow = base0 + row;
        if (grow >= NN) grow = NN - 1;             // junk ok, stores guarded
        H8 h = *reinterpret_cast<const H8*>(&g_ha[(size_t)grow * 32 + c * 4]);
        *reinterpret_cast<H8*>(&sA[row * 64 + ((c ^ (row & 7)) * 8)]) = h;
    }
    __syncthreads();

    int warp = tid >> 5;
    int lane = tid & 31;
    int wrow = warp * 16;

    float acc[8][4];
#pragma unroll
    for (int n = 0; n < 8; n++)
#pragma unroll
        for (int j = 0; j < 4; j++) acc[n][j] = 0.0f;

    int a_t = lane >> 3, a_r = lane & 7;
    int a_row = wrow + (a_t & 1) * 8 + a_r;
    int a_chsel = a_t >> 1;
    int b_kr = (a_t & 1) * 8 + a_r;
    int b_csel = a_t >> 1;

#pragma unroll
    for (int kc = 0; kc < 4; kc++) {
        unsigned a0, a1, a2, a3;
        {
            int chunk = 2 * kc + a_chsel;
            unsigned addr = smem_u32(&sA[a_row * 64 + ((chunk ^ (a_row & 7)) * 8)]);
            asm volatile("ldmatrix.sync.aligned.m8n8.x4.shared.b16 {%0,%1,%2,%3}, [%4];"
                         : "=r"(a0), "=r"(a1), "=r"(a2), "=r"(a3) : "r"(addr));
        }
        int krow = 16 * kc + b_kr;
#pragma unroll
        for (int np = 0; np < 4; np++) {
            unsigned b0, b1, b2, b3;
            int chunk = 2 * np + b_csel;
            unsigned addr = smem_u32(&sW[krow * 64 + ((chunk ^ (krow & 7)) * 8)]);
            asm volatile("ldmatrix.sync.aligned.m8n8.x4.trans.shared.b16 {%0,%1,%2,%3}, [%4];"
                         : "=r"(b0), "=r"(b1), "=r"(b2), "=r"(b3) : "r"(addr));
            asm volatile("mma.sync.aligned.m16n8k16.row.col.f32.f16.f16.f32 "
                         "{%0,%1,%2,%3}, {%4,%5,%6,%7}, {%8,%9}, {%0,%1,%2,%3};"
                         : "+f"(acc[2 * np][0]), "+f"(acc[2 * np][1]),
                           "+f"(acc[2 * np][2]), "+f"(acc[2 * np][3])
                         : "r"(a0), "r"(a1), "r"(a2), "r"(a3), "r"(b0), "r"(b1));
            asm volatile("mma.sync.aligned.m16n8k16.row.col.f32.f16.f16.f32 "
                         "{%0,%1,%2,%3}, {%4,%5,%6,%7}, {%8,%9}, {%0,%1,%2,%3};"
                         : "+f"(acc[2 * np + 1][0]), "+f"(acc[2 * np + 1][1]),
                           "+f"(acc[2 * np + 1][2]), "+f"(acc[2 * np + 1][3])
                         : "r"(a0), "r"(a1), "r"(a2), "r"(a3), "r"(b2), "r"(b3));
        }
    }

    // Epilogue: c = nt*8 + (lane&3)*2 (+1). nt<4 → mu, nt>=4 → lv.
    int r0 = wrow + (lane >> 2);
    int cq = lane & 3;
#pragma unroll
    for (int half = 0; half < 2; half++) {
        int node = base0 + r0 + half * 8;
        if (node < NN) {
#pragma unroll
            for (int nt = 0; nt < 8; nt++) {
                int c = nt * 8 + cq * 2;
                float2 v;
                v.x = acc[nt][2 * half + 0] + sB[c];
                v.y = acc[nt][2 * half + 1] + sB[c + 1];
                if (c < 32)
                    *reinterpret_cast<float2*>(&out[(size_t)node * LAT + c]) = v;
                else
                    *reinterpret_cast<float2*>(
                        &out[(size_t)NN * LAT + (size_t)node * LAT + (c - 32)]) = v;
            }
        }
    }
}

// ---------------------------------------------------------------------------
extern "C" void kernel_launch(void* const* d_in, const int* in_sizes, int n_in,
                              void* d_out, int out_size) {
    const float* x    = (const float*)d_in[0];
    const int*   ei   = (const int*)d_in[1];    // int32 or int64 (detected)
    const float* W1   = (const float*)d_in[2];
    const float* b1   = (const float*)d_in[3];
    const float* Wmu  = (const float*)d_in[4];
    const float* bmu  = (const float*)d_in[5];
    const float* Wlv  = (const float*)d_in[6];
    const float* blv  = (const float*)d_in[7];
    float*       out  = (float*)d_out;

    k_zero_detect<<<(NN + 255) / 256, 256>>>(ei);       // 1
    k_count_deg<<<(NE + 255) / 256, 256>>>(ei);         // 2
    k_scan_local<<<SCAN_NB, SCAN_BLK>>>();              // 3 (also dis)
    k_gemm1<<<(NN + 127) / 128, 256>>>(x, W1);          // 4 ← ncu profiles this
    k_finalize_csr<<<(NN + 255) / 256, 256>>>();        // 5
    k_scatter<<<(NE + 255) / 256, 256>>>(ei);           // 6
    k_agg1<<<NN / 8, 256>>>(b1);                        // 7
    k_agg2<<<NN / 8, 256>>>();                          // 8
    k_gemm2<<<(NN + 127) / 128, 256>>>(Wmu, bmu, Wlv, blv, out);  // 9
}